// round 2
// baseline (speedup 1.0000x reference)
#include <cuda_runtime.h>

// ---------------------------------------------------------------------------
// ExtendedGCN: 3-layer GCN (PyG GCNConv semantics) + softmax.
//   dinv[i]  = rsqrt(indeg(i) + 1)            (deg from dst edges + self-loop)
//   layerK:  H = X @ Wk
//            out[i] = b_k + dinv[i]^2 * H[i] + sum_{e: j->i} dinv[j]*dinv[i]*H[j]
//   relu after layer1 only; softmax(dim=1) after layer3.
// NOTE: edge_index is int32 on device (JAX x64 disabled -> int64 request
// silently becomes int32).
// ---------------------------------------------------------------------------

#define NMAX 50000
#define EMAX 800000

__device__ float g_H[(size_t)NMAX * 128];   // X @ W scratch (max dim 128)
__device__ float g_A[(size_t)NMAX * 128];   // layer1 output / layer3 logits
__device__ float g_B[(size_t)NMAX * 64];    // layer2 output
__device__ float g_dinv[NMAX];
__device__ int   g_deg[NMAX];
__device__ float g_norm[EMAX];

// ------------------------------- degree / norm ----------------------------

__global__ void zero_deg_kernel(int n) {
    int i = blockIdx.x * blockDim.x + threadIdx.x;
    if (i < n) g_deg[i] = 0;
}

__global__ void deg_kernel(const int* __restrict__ dst, int E) {
    int e = blockIdx.x * blockDim.x + threadIdx.x;
    if (e < E) atomicAdd(&g_deg[dst[e]], 1);
}

__global__ void dinv_kernel(int n) {
    int i = blockIdx.x * blockDim.x + threadIdx.x;
    if (i < n) g_dinv[i] = rsqrtf((float)(g_deg[i] + 1));
}

__global__ void norm_kernel(const int* __restrict__ src,
                            const int* __restrict__ dst, int E) {
    int e = blockIdx.x * blockDim.x + threadIdx.x;
    if (e < E) g_norm[e] = g_dinv[src[e]] * g_dinv[dst[e]];
}

// ------------------------------- SGEMM ------------------------------------
// C[M,N] = A[M,K] @ W[K,N].  Register-blocked tiled fp32 GEMM.

template <int BM, int BN, int BK, int TM, int TN>
__global__ void gemm_kernel(const float* __restrict__ A,
                            const float* __restrict__ W,
                            float* __restrict__ C, int M, int K, int N) {
    constexpr int THREADS = (BM / TM) * (BN / TN);
    __shared__ float As[BM][BK + 1];
    __shared__ float Ws[BK][BN];

    const int block_row = blockIdx.y * BM;
    const int block_col = blockIdx.x * BN;
    const int tid = threadIdx.x;
    const int tx = tid % (BN / TN);
    const int ty = tid / (BN / TN);

    float acc[TM][TN];
#pragma unroll
    for (int i = 0; i < TM; i++)
#pragma unroll
        for (int j = 0; j < TN; j++) acc[i][j] = 0.0f;

    for (int k0 = 0; k0 < K; k0 += BK) {
#pragma unroll
        for (int i = tid; i < BM * BK; i += THREADS) {
            int r = i / BK, c = i % BK;
            int gr = block_row + r;
            As[r][c] = (gr < M) ? A[(size_t)gr * K + k0 + c] : 0.0f;
        }
#pragma unroll
        for (int i = tid; i < BK * BN; i += THREADS) {
            int r = i / BN, c = i % BN;
            Ws[r][c] = W[(size_t)(k0 + r) * N + block_col + c];
        }
        __syncthreads();

#pragma unroll
        for (int k = 0; k < BK; k++) {
            float ra[TM], rb[TN];
#pragma unroll
            for (int i = 0; i < TM; i++) ra[i] = As[ty * TM + i][k];
#pragma unroll
            for (int j = 0; j < TN; j++) rb[j] = Ws[k][tx * TN + j];
#pragma unroll
            for (int i = 0; i < TM; i++)
#pragma unroll
                for (int j = 0; j < TN; j++) acc[i][j] += ra[i] * rb[j];
        }
        __syncthreads();
    }

#pragma unroll
    for (int i = 0; i < TM; i++) {
        int gr = block_row + ty * TM + i;
        if (gr < M) {
#pragma unroll
            for (int j = 0; j < TN; j++)
                C[(size_t)gr * N + block_col + tx * TN + j] = acc[i][j];
        }
    }
}

// --------------------------- aggregation ----------------------------------
// init: out[i] = b + dinv[i]^2 * H[i]   (self-loop term + bias, no atomics)

template <int D>
__global__ void init_out_kernel(float* __restrict__ out,
                                const float* __restrict__ H,
                                const float* __restrict__ b, int n) {
    constexpr int L = D / 4;
    int t = blockIdx.x * blockDim.x + threadIdx.x;
    if (t >= n * L) return;
    int i = t / L, f = t % L;
    float di = g_dinv[i];
    float s = di * di;
    float4 h = ((const float4*)H)[(size_t)i * L + f];
    float4 bb = ((const float4*)b)[f];
    float4 o;
    o.x = bb.x + s * h.x;
    o.y = bb.y + s * h.y;
    o.z = bb.z + s * h.z;
    o.w = bb.w + s * h.w;
    ((float4*)out)[(size_t)i * L + f] = o;
}

// edge scatter: out[dst] += norm[e] * H[src].  One float4 per thread.
// atomicAdd with unused result -> REDG (no return path).

template <int D>
__global__ void edge_agg_kernel(float* __restrict__ out,
                                const float* __restrict__ H,
                                const int* __restrict__ src,
                                const int* __restrict__ dst, long long total) {
    constexpr int L = D / 4;
    long long t = (long long)blockIdx.x * blockDim.x + threadIdx.x;
    if (t >= total) return;
    int e = (int)(t / L);
    int f = (int)(t % L);
    int s = src[e];
    int d = dst[e];
    float nrm = g_norm[e];
    float4 h = ((const float4*)H)[(size_t)s * L + f];
    float* o = out + (size_t)d * D + f * 4;
    atomicAdd(o + 0, nrm * h.x);
    atomicAdd(o + 1, nrm * h.y);
    atomicAdd(o + 2, nrm * h.z);
    atomicAdd(o + 3, nrm * h.w);
}

__global__ void relu_kernel(float* __restrict__ a, int total4) {
    int t = blockIdx.x * blockDim.x + threadIdx.x;
    if (t >= total4) return;
    float4 v = ((float4*)a)[t];
    v.x = fmaxf(v.x, 0.0f);
    v.y = fmaxf(v.y, 0.0f);
    v.z = fmaxf(v.z, 0.0f);
    v.w = fmaxf(v.w, 0.0f);
    ((float4*)a)[t] = v;
}

// ------------------------------- softmax ----------------------------------

__global__ void softmax16_kernel(const float* __restrict__ logits,
                                 float* __restrict__ out, int n) {
    int i = blockIdx.x * blockDim.x + threadIdx.x;
    if (i >= n) return;
    const float4* p = (const float4*)(logits + (size_t)i * 16);
    float4 a = p[0], b = p[1], c = p[2], d = p[3];
    float v[16] = {a.x, a.y, a.z, a.w, b.x, b.y, b.z, b.w,
                   c.x, c.y, c.z, c.w, d.x, d.y, d.z, d.w};
    float m = v[0];
#pragma unroll
    for (int k = 1; k < 16; k++) m = fmaxf(m, v[k]);
    float sum = 0.0f;
#pragma unroll
    for (int k = 0; k < 16; k++) {
        v[k] = __expf(v[k] - m);
        sum += v[k];
    }
    float inv = 1.0f / sum;
    float4* q = (float4*)(out + (size_t)i * 16);
    q[0] = make_float4(v[0] * inv, v[1] * inv, v[2] * inv, v[3] * inv);
    q[1] = make_float4(v[4] * inv, v[5] * inv, v[6] * inv, v[7] * inv);
    q[2] = make_float4(v[8] * inv, v[9] * inv, v[10] * inv, v[11] * inv);
    q[3] = make_float4(v[12] * inv, v[13] * inv, v[14] * inv, v[15] * inv);
}

// ------------------------------- launch -----------------------------------

extern "C" void kernel_launch(void* const* d_in, const int* in_sizes, int n_in,
                              void* d_out, int out_size) {
    const float* x  = (const float*)d_in[0];
    const int*   ei = (const int*)d_in[1];      // int32! (JAX x64 disabled)
    const float* W1 = (const float*)d_in[2];
    const float* b1 = (const float*)d_in[3];
    const float* W2 = (const float*)d_in[4];
    const float* b2 = (const float*)d_in[5];
    const float* W3 = (const float*)d_in[6];
    const float* b3 = (const float*)d_in[7];

    const int n = in_sizes[0] / 128;
    const int E = in_sizes[1] / 2;
    const int* src = ei;
    const int* dst = ei + E;

    float *H, *A, *B;
    cudaGetSymbolAddress((void**)&H, g_H);
    cudaGetSymbolAddress((void**)&A, g_A);
    cudaGetSymbolAddress((void**)&B, g_B);

    const int T = 256;
    auto blocks = [&](long long work) { return (int)((work + T - 1) / T); };

    // graph normalization (recomputed every call; graph-replay safe)
    zero_deg_kernel<<<blocks(n), T>>>(n);
    deg_kernel<<<blocks(E), T>>>(dst, E);
    dinv_kernel<<<blocks(n), T>>>(n);
    norm_kernel<<<blocks(E), T>>>(src, dst, E);

    // ----- layer 1: 128 -> 128, relu -----
    {
        dim3 grid(128 / 64, (n + 63) / 64);
        gemm_kernel<64, 64, 32, 4, 4><<<grid, 256>>>(x, W1, H, n, 128, 128);
    }
    init_out_kernel<128><<<blocks((long long)n * 32), T>>>(A, H, b1, n);
    edge_agg_kernel<128><<<blocks((long long)E * 32), T>>>(A, H, src, dst, (long long)E * 32);
    relu_kernel<<<blocks((long long)n * 32), T>>>(A, n * 32);

    // ----- layer 2: 128 -> 64 -----
    {
        dim3 grid(64 / 64, (n + 63) / 64);
        gemm_kernel<64, 64, 32, 4, 4><<<grid, 256>>>(A, W2, H, n, 128, 64);
    }
    init_out_kernel<64><<<blocks((long long)n * 16), T>>>(B, H, b2, n);
    edge_agg_kernel<64><<<blocks((long long)E * 16), T>>>(B, H, src, dst, (long long)E * 16);

    // ----- layer 3: 64 -> 16 -----
    {
        dim3 grid(16 / 16, (n + 63) / 64);
        gemm_kernel<64, 16, 32, 4, 1><<<grid, 256>>>(B, W3, H, n, 64, 16);
    }
    init_out_kernel<16><<<blocks((long long)n * 4), T>>>(A, H, b3, n);
    edge_agg_kernel<16><<<blocks((long long)E * 4), T>>>(A, H, src, dst, (long long)E * 4);

    // ----- softmax -> d_out -----
    softmax16_kernel<<<blocks(n), T>>>(A, (float*)d_out, n);
}

// round 3
// speedup vs baseline: 2.1476x; 2.1476x over previous
#include <cuda_runtime.h>

// ---------------------------------------------------------------------------
// ExtendedGCN: 3-layer GCN (PyG GCNConv) + softmax, atomic-free pull design.
//   dinv[i] = rsqrt(indeg(i)+1)
//   layerK: H = X @ Wk ;  out[i] = b + dinv[i]^2 H[i] + sum_{j->i} dinv_j dinv_i H[j]
//   CSR-by-dst built per call; aggregation = register-accumulated gather.
//   relu fused into layer1 agg; softmax fused into layer3 agg.
// edge_index is int32 on device (JAX x64 disabled).
// ---------------------------------------------------------------------------

#define NMAX 50000
#define EMAX 800000
#define SCAN_B 1024

__device__ float g_H[(size_t)NMAX * 128];   // X @ W scratch
__device__ float g_A[(size_t)NMAX * 128];   // layer outputs (ping)
__device__ float g_B[(size_t)NMAX * 64];    // layer outputs (pong)
__device__ float g_dinv[NMAX];
__device__ int   g_deg[NMAX];
__device__ int   g_offs[NMAX + 1];
__device__ int   g_cursor[NMAX];
__device__ int   g_csr_src[EMAX];
__device__ int   g_bsum[(NMAX + SCAN_B - 1) / SCAN_B];
__device__ int   g_bpre[(NMAX + SCAN_B - 1) / SCAN_B];

// ----------------------------- CSR build ----------------------------------

__global__ void zero_deg_kernel(int n) {
    int i = blockIdx.x * blockDim.x + threadIdx.x;
    if (i < n) g_deg[i] = 0;
}

__global__ void deg_kernel(const int* __restrict__ dst, int E) {
    int e = blockIdx.x * blockDim.x + threadIdx.x;
    if (e < E) atomicAdd(&g_deg[dst[e]], 1);
}

__global__ void dinv_kernel(int n) {
    int i = blockIdx.x * blockDim.x + threadIdx.x;
    if (i < n) g_dinv[i] = rsqrtf((float)(g_deg[i] + 1));
}

// per-block exclusive scan of deg -> offs, block totals -> g_bsum
__global__ void scan1_kernel(int n) {
    __shared__ int sm[SCAN_B];
    int tid = threadIdx.x;
    int gid = blockIdx.x * SCAN_B + tid;
    int v = (gid < n) ? g_deg[gid] : 0;
    sm[tid] = v;
    __syncthreads();
#pragma unroll
    for (int off = 1; off < SCAN_B; off <<= 1) {
        int t = (tid >= off) ? sm[tid - off] : 0;
        __syncthreads();
        sm[tid] += t;
        __syncthreads();
    }
    if (gid < n) g_offs[gid] = sm[tid] - v;   // exclusive
    if (tid == SCAN_B - 1) g_bsum[blockIdx.x] = sm[tid];
}

__global__ void scan2_kernel(int nblocks) {   // tiny serial scan
    if (threadIdx.x == 0 && blockIdx.x == 0) {
        int acc = 0;
        for (int b = 0; b < nblocks; b++) {
            g_bpre[b] = acc;
            acc += g_bsum[b];
        }
    }
}

__global__ void scan3_kernel(int n, int E) {
    int gid = blockIdx.x * blockDim.x + threadIdx.x;
    if (gid < n) {
        int o = g_offs[gid] + g_bpre[gid / SCAN_B];
        g_offs[gid] = o;
        g_cursor[gid] = o;
    }
    if (gid == n) g_offs[n] = E;
}

__global__ void scatter_kernel(const int* __restrict__ src,
                               const int* __restrict__ dst, int E) {
    int e = blockIdx.x * blockDim.x + threadIdx.x;
    if (e < E) {
        int pos = atomicAdd(&g_cursor[dst[e]], 1);
        g_csr_src[pos] = src[e];
    }
}

// ------------------------------- SGEMM ------------------------------------

template <int BM, int BN, int BK, int TM, int TN>
__global__ void gemm_kernel(const float* __restrict__ A,
                            const float* __restrict__ W,
                            float* __restrict__ C, int M, int K, int N) {
    constexpr int THREADS = (BM / TM) * (BN / TN);
    __shared__ float As[BM][BK + 1];
    __shared__ float Ws[BK][BN];

    const int block_row = blockIdx.y * BM;
    const int block_col = blockIdx.x * BN;
    const int tid = threadIdx.x;
    const int tx = tid % (BN / TN);
    const int ty = tid / (BN / TN);

    float acc[TM][TN];
#pragma unroll
    for (int i = 0; i < TM; i++)
#pragma unroll
        for (int j = 0; j < TN; j++) acc[i][j] = 0.0f;

    for (int k0 = 0; k0 < K; k0 += BK) {
#pragma unroll
        for (int i = tid; i < BM * BK; i += THREADS) {
            int r = i / BK, c = i % BK;
            int gr = block_row + r;
            As[r][c] = (gr < M) ? A[(size_t)gr * K + k0 + c] : 0.0f;
        }
#pragma unroll
        for (int i = tid; i < BK * BN; i += THREADS) {
            int r = i / BN, c = i % BN;
            Ws[r][c] = W[(size_t)(k0 + r) * N + block_col + c];
        }
        __syncthreads();

#pragma unroll
        for (int k = 0; k < BK; k++) {
            float ra[TM], rb[TN];
#pragma unroll
            for (int i = 0; i < TM; i++) ra[i] = As[ty * TM + i][k];
#pragma unroll
            for (int j = 0; j < TN; j++) rb[j] = Ws[k][tx * TN + j];
#pragma unroll
            for (int i = 0; i < TM; i++)
#pragma unroll
                for (int j = 0; j < TN; j++) acc[i][j] += ra[i] * rb[j];
        }
        __syncthreads();
    }

#pragma unroll
    for (int i = 0; i < TM; i++) {
        int gr = block_row + ty * TM + i;
        if (gr < M) {
#pragma unroll
            for (int j = 0; j < TN; j++)
                C[(size_t)gr * N + block_col + tx * TN + j] = acc[i][j];
        }
    }
}

// ------------------------ gather aggregation ------------------------------
// LPN = D/4 lanes cooperate on one node; each lane owns one float4 column
// slice. acc = b + dinv^2*H[i] + sum_e dinv_i*dinv_s*H[s]. No atomics.

template <int D, bool RELU, bool SOFTMAX>
__global__ void agg_gather_kernel(float* __restrict__ out,
                                  const float* __restrict__ H,
                                  const float* __restrict__ b, int n) {
    constexpr int LPN = D / 4;       // lanes per node
    constexpr int NPW = 32 / LPN;    // nodes per warp
    int warp = (blockIdx.x * blockDim.x + threadIdx.x) >> 5;
    int lane = threadIdx.x & 31;
    int grp = lane / LPN;
    int f = lane % LPN;
    int i = warp * NPW + grp;
    if (i >= n) return;

    float di = g_dinv[i];
    float s2 = di * di;
    float4 h = ((const float4*)H)[(size_t)i * LPN + f];
    float4 bb = ((const float4*)b)[f];
    float4 acc;
    acc.x = bb.x + s2 * h.x;
    acc.y = bb.y + s2 * h.y;
    acc.z = bb.z + s2 * h.z;
    acc.w = bb.w + s2 * h.w;

    int beg = g_offs[i], end = g_offs[i + 1];
#pragma unroll 4
    for (int e = beg; e < end; e++) {
        int s = __ldg(&g_csr_src[e]);
        float nrm = di * __ldg(&g_dinv[s]);
        float4 v = ((const float4*)H)[(size_t)s * LPN + f];
        acc.x += nrm * v.x;
        acc.y += nrm * v.y;
        acc.z += nrm * v.z;
        acc.w += nrm * v.w;
    }

    if (RELU) {
        acc.x = fmaxf(acc.x, 0.0f);
        acc.y = fmaxf(acc.y, 0.0f);
        acc.z = fmaxf(acc.z, 0.0f);
        acc.w = fmaxf(acc.w, 0.0f);
    }

    if (SOFTMAX) {
        // D==16: 4 lanes per node hold the 16 logits; reduce across width 4.
        float m = fmaxf(fmaxf(acc.x, acc.y), fmaxf(acc.z, acc.w));
#pragma unroll
        for (int o = 1; o < LPN; o <<= 1)
            m = fmaxf(m, __shfl_xor_sync(0xFFFFFFFFu, m, o, LPN));
        acc.x = __expf(acc.x - m);
        acc.y = __expf(acc.y - m);
        acc.z = __expf(acc.z - m);
        acc.w = __expf(acc.w - m);
        float s = acc.x + acc.y + acc.z + acc.w;
#pragma unroll
        for (int o = 1; o < LPN; o <<= 1)
            s += __shfl_xor_sync(0xFFFFFFFFu, s, o, LPN);
        float inv = 1.0f / s;
        acc.x *= inv;
        acc.y *= inv;
        acc.z *= inv;
        acc.w *= inv;
    }

    ((float4*)out)[(size_t)i * LPN + f] = acc;
}

// ------------------------------- launch -----------------------------------

extern "C" void kernel_launch(void* const* d_in, const int* in_sizes, int n_in,
                              void* d_out, int out_size) {
    const float* x  = (const float*)d_in[0];
    const int*   ei = (const int*)d_in[1];   // int32 (JAX x64 disabled)
    const float* W1 = (const float*)d_in[2];
    const float* b1 = (const float*)d_in[3];
    const float* W2 = (const float*)d_in[4];
    const float* b2 = (const float*)d_in[5];
    const float* W3 = (const float*)d_in[6];
    const float* b3 = (const float*)d_in[7];

    const int n = in_sizes[0] / 128;
    const int E = in_sizes[1] / 2;
    const int* src = ei;
    const int* dst = ei + E;

    float *H, *A, *B;
    cudaGetSymbolAddress((void**)&H, g_H);
    cudaGetSymbolAddress((void**)&A, g_A);
    cudaGetSymbolAddress((void**)&B, g_B);

    const int T = 256;
    auto blocks = [&](long long work) { return (int)((work + T - 1) / T); };
    const int nScanBlocks = (n + SCAN_B - 1) / SCAN_B;

    // ----- CSR build (per call; graph-replay safe) -----
    zero_deg_kernel<<<blocks(n), T>>>(n);
    deg_kernel<<<blocks(E), T>>>(dst, E);
    dinv_kernel<<<blocks(n), T>>>(n);
    scan1_kernel<<<nScanBlocks, SCAN_B>>>(n);
    scan2_kernel<<<1, 1>>>(nScanBlocks);
    scan3_kernel<<<blocks(n + 1), T>>>(n, E);
    scatter_kernel<<<blocks(E), T>>>(src, dst, E);

    // ----- layer 1: 128 -> 128, relu -----
    {
        dim3 grid(128 / 64, (n + 63) / 64);
        gemm_kernel<64, 64, 32, 4, 4><<<grid, 256>>>(x, W1, H, n, 128, 128);
    }
    agg_gather_kernel<128, true, false>
        <<<blocks((long long)n * 32), T>>>(A, H, b1, n);

    // ----- layer 2: 128 -> 64 -----
    {
        dim3 grid(64 / 64, (n + 63) / 64);
        gemm_kernel<64, 64, 32, 4, 4><<<grid, 256>>>(A, W2, H, n, 128, 64);
    }
    agg_gather_kernel<64, false, false>
        <<<blocks((long long)n * 16), T>>>(B, H, b2, n);

    // ----- layer 3: 64 -> 16 + softmax -> d_out -----
    {
        dim3 grid(16 / 16, (n + 63) / 64);
        gemm_kernel<64, 16, 32, 4, 1><<<grid, 256>>>(B, W3, H, n, 64, 16);
    }
    agg_gather_kernel<16, false, true>
        <<<blocks((long long)n * 4), T>>>((float*)d_out, H, b3, n);
}

// round 4
// speedup vs baseline: 2.5591x; 1.1916x over previous
#include <cuda_runtime.h>

// ---------------------------------------------------------------------------
// ExtendedGCN: 3-layer GCN (PyG GCNConv) + softmax, atomic-free pull design.
//   dinv[i] = rsqrt(indeg(i)+1)
//   layerK: H = X @ Wk ;  out[i] = b + dinv[i]^2 H[i] + sum_{j->i} dinv_j dinv_i H[j]
//   CSR-by-dst with packed (src, norm) payload; register-accumulated gather.
//   relu fused into layer1 agg; softmax fused into layer3 agg.
// edge_index is int32 on device (JAX x64 disabled).
// ---------------------------------------------------------------------------

#define NMAX 50000
#define EMAX 800000
#define SCAN_B 1024

__device__ float  g_H[(size_t)NMAX * 128];   // X @ W scratch
__device__ float  g_A[(size_t)NMAX * 128];   // layer outputs (ping)
__device__ float  g_B[(size_t)NMAX * 64];    // layer outputs (pong)
__device__ float  g_dinv[NMAX];
__device__ int    g_deg[NMAX];
__device__ int    g_offs[NMAX + 1];
__device__ int    g_cursor[NMAX];
__device__ float2 g_csr[EMAX];               // (src as int bits, norm)
__device__ int    g_bsum[(NMAX + SCAN_B - 1) / SCAN_B];
__device__ int    g_bpre[(NMAX + SCAN_B - 1) / SCAN_B];

// ----------------------------- CSR build ----------------------------------

__global__ void zero_deg_kernel(int n) {
    int i = blockIdx.x * blockDim.x + threadIdx.x;
    if (i < n) g_deg[i] = 0;
}

__global__ void deg_kernel(const int* __restrict__ dst, int E) {
    int e = blockIdx.x * blockDim.x + threadIdx.x;
    if (e < E) atomicAdd(&g_deg[dst[e]], 1);
}

__global__ void dinv_kernel(int n) {
    int i = blockIdx.x * blockDim.x + threadIdx.x;
    if (i < n) g_dinv[i] = rsqrtf((float)(g_deg[i] + 1));
}

// warp-shuffle block scan: exclusive scan of deg -> offs, totals -> g_bsum
__global__ void scan1_kernel(int n) {
    __shared__ int warp_tot[32];
    int tid = threadIdx.x;
    int lane = tid & 31;
    int warp = tid >> 5;
    int gid = blockIdx.x * SCAN_B + tid;
    int v = (gid < n) ? g_deg[gid] : 0;

    int inc = v;                      // inclusive warp scan
#pragma unroll
    for (int o = 1; o < 32; o <<= 1) {
        int t = __shfl_up_sync(0xFFFFFFFFu, inc, o);
        if (lane >= o) inc += t;
    }
    if (lane == 31) warp_tot[warp] = inc;
    __syncthreads();
    if (warp == 0) {
        int w = warp_tot[lane];
        int wi = w;
#pragma unroll
        for (int o = 1; o < 32; o <<= 1) {
            int t = __shfl_up_sync(0xFFFFFFFFu, wi, o);
            if (lane >= o) wi += t;
        }
        warp_tot[lane] = wi - w;      // exclusive warp prefix
        if (lane == 31) g_bsum[blockIdx.x] = wi;
    }
    __syncthreads();
    if (gid < n) g_offs[gid] = inc - v + warp_tot[warp];
}

__global__ void scan2_kernel(int nblocks) {   // tiny serial scan
    if (threadIdx.x == 0 && blockIdx.x == 0) {
        int acc = 0;
        for (int b = 0; b < nblocks; b++) {
            g_bpre[b] = acc;
            acc += g_bsum[b];
        }
    }
}

__global__ void scan3_kernel(int n, int E) {
    int gid = blockIdx.x * blockDim.x + threadIdx.x;
    if (gid < n) {
        int o = g_offs[gid] + g_bpre[gid / SCAN_B];
        g_offs[gid] = o;
        g_cursor[gid] = o;
    }
    if (gid == n) g_offs[n] = E;
}

__global__ void scatter_kernel(const int* __restrict__ src,
                               const int* __restrict__ dst, int E) {
    int e = blockIdx.x * blockDim.x + threadIdx.x;
    if (e < E) {
        int s = src[e], d = dst[e];
        int pos = atomicAdd(&g_cursor[d], 1);
        float nrm = g_dinv[s] * g_dinv[d];
        g_csr[pos] = make_float2(__int_as_float(s), nrm);
    }
}

// ------------------------------- SGEMM ------------------------------------
// C[M,N] = A[M,K] @ W[K,N]. BMxBNxBK tile, TMxTN per thread, float4 smem ops.
// Requires: K % BK == 0, N % BN == 0, TM%4==0, TN%4==0, BK%4==0.

template <int BM, int BN, int BK, int TM, int TN>
__global__ void gemm_kernel(const float* __restrict__ A,
                            const float* __restrict__ W,
                            float* __restrict__ C, int M, int K, int N) {
    constexpr int THREADS = (BM / TM) * (BN / TN);
    __shared__ float As[BK][BM];     // A staged transposed
    __shared__ float Ws[BK][BN];

    const int block_row = blockIdx.y * BM;
    const int block_col = blockIdx.x * BN;
    const int tid = threadIdx.x;
    const int tx = tid % (BN / TN);
    const int ty = tid / (BN / TN);

    // A-load mapping: BK/4 float4 per row
    constexpr int A_F4_PER_ROW = BK / 4;
    const int a_row0 = tid / A_F4_PER_ROW;
    const int a_col = (tid % A_F4_PER_ROW) * 4;
    constexpr int A_ROW_STRIDE = THREADS / A_F4_PER_ROW;

    // W-load mapping: BN/4 float4 per row
    constexpr int W_F4_PER_ROW = BN / 4;
    const int w_row0 = tid / W_F4_PER_ROW;
    const int w_col = (tid % W_F4_PER_ROW) * 4;
    constexpr int W_ROW_STRIDE = THREADS / W_F4_PER_ROW;

    float acc[TM][TN];
#pragma unroll
    for (int i = 0; i < TM; i++)
#pragma unroll
        for (int j = 0; j < TN; j++) acc[i][j] = 0.0f;

    for (int k0 = 0; k0 < K; k0 += BK) {
#pragma unroll
        for (int r = a_row0; r < BM; r += A_ROW_STRIDE) {
            int gr = block_row + r;
            float4 v = (gr < M)
                ? *(const float4*)&A[(size_t)gr * K + k0 + a_col]
                : make_float4(0.f, 0.f, 0.f, 0.f);
            As[a_col + 0][r] = v.x;
            As[a_col + 1][r] = v.y;
            As[a_col + 2][r] = v.z;
            As[a_col + 3][r] = v.w;
        }
#pragma unroll
        for (int r = w_row0; r < BK; r += W_ROW_STRIDE) {
            *(float4*)&Ws[r][w_col] =
                *(const float4*)&W[(size_t)(k0 + r) * N + block_col + w_col];
        }
        __syncthreads();

#pragma unroll
        for (int k = 0; k < BK; k++) {
            float ra[TM], rb[TN];
#pragma unroll
            for (int i = 0; i < TM; i += 4)
                *(float4*)&ra[i] = *(const float4*)&As[k][ty * TM + i];
#pragma unroll
            for (int j = 0; j < TN; j += 4)
                *(float4*)&rb[j] = *(const float4*)&Ws[k][tx * TN + j];
#pragma unroll
            for (int i = 0; i < TM; i++)
#pragma unroll
                for (int j = 0; j < TN; j++) acc[i][j] += ra[i] * rb[j];
        }
        __syncthreads();
    }

#pragma unroll
    for (int i = 0; i < TM; i++) {
        int gr = block_row + ty * TM + i;
        if (gr < M) {
#pragma unroll
            for (int j = 0; j < TN; j += 4)
                *(float4*)&C[(size_t)gr * N + block_col + tx * TN + j] =
                    *(float4*)&acc[i][j];
        }
    }
}

// ------------------------ gather aggregation ------------------------------
// LPN = D/4 lanes per node; each lane owns one float4 column slice.
// acc = b + dinv^2*H[i] + sum_e norm_e*H[src_e]. No atomics, norm precomputed.

template <int D, bool RELU, bool SOFTMAX>
__global__ void agg_gather_kernel(float* __restrict__ out,
                                  const float* __restrict__ H,
                                  const float* __restrict__ b, int n) {
    constexpr int LPN = D / 4;       // lanes per node
    constexpr int NPW = 32 / LPN;    // nodes per warp
    int warp = (blockIdx.x * blockDim.x + threadIdx.x) >> 5;
    int lane = threadIdx.x & 31;
    int grp = lane / LPN;
    int f = lane % LPN;
    int i = warp * NPW + grp;
    if (i >= n) return;

    float di = g_dinv[i];
    float s2 = di * di;
    float4 h = ((const float4*)H)[(size_t)i * LPN + f];
    float4 bb = ((const float4*)b)[f];
    float4 acc;
    acc.x = bb.x + s2 * h.x;
    acc.y = bb.y + s2 * h.y;
    acc.z = bb.z + s2 * h.z;
    acc.w = bb.w + s2 * h.w;

    int beg = g_offs[i], end = g_offs[i + 1];
#pragma unroll 4
    for (int e = beg; e < end; e++) {
        float2 p = __ldg(&g_csr[e]);
        int s = __float_as_int(p.x);
        float nrm = p.y;
        float4 v = ((const float4*)H)[(size_t)s * LPN + f];
        acc.x += nrm * v.x;
        acc.y += nrm * v.y;
        acc.z += nrm * v.z;
        acc.w += nrm * v.w;
    }

    if (RELU) {
        acc.x = fmaxf(acc.x, 0.0f);
        acc.y = fmaxf(acc.y, 0.0f);
        acc.z = fmaxf(acc.z, 0.0f);
        acc.w = fmaxf(acc.w, 0.0f);
    }

    if (SOFTMAX) {
        // D==16: 4 lanes per node hold the 16 logits; reduce across width 4.
        float m = fmaxf(fmaxf(acc.x, acc.y), fmaxf(acc.z, acc.w));
#pragma unroll
        for (int o = 1; o < LPN; o <<= 1)
            m = fmaxf(m, __shfl_xor_sync(0xFFFFFFFFu, m, o, LPN));
        acc.x = __expf(acc.x - m);
        acc.y = __expf(acc.y - m);
        acc.z = __expf(acc.z - m);
        acc.w = __expf(acc.w - m);
        float s = acc.x + acc.y + acc.z + acc.w;
#pragma unroll
        for (int o = 1; o < LPN; o <<= 1)
            s += __shfl_xor_sync(0xFFFFFFFFu, s, o, LPN);
        float inv = 1.0f / s;
        acc.x *= inv;
        acc.y *= inv;
        acc.z *= inv;
        acc.w *= inv;
    }

    ((float4*)out)[(size_t)i * LPN + f] = acc;
}

// ------------------------------- launch -----------------------------------

extern "C" void kernel_launch(void* const* d_in, const int* in_sizes, int n_in,
                              void* d_out, int out_size) {
    const float* x  = (const float*)d_in[0];
    const int*   ei = (const int*)d_in[1];   // int32 (JAX x64 disabled)
    const float* W1 = (const float*)d_in[2];
    const float* b1 = (const float*)d_in[3];
    const float* W2 = (const float*)d_in[4];
    const float* b2 = (const float*)d_in[5];
    const float* W3 = (const float*)d_in[6];
    const float* b3 = (const float*)d_in[7];

    const int n = in_sizes[0] / 128;
    const int E = in_sizes[1] / 2;
    const int* src = ei;
    const int* dst = ei + E;

    float *H, *A, *B;
    cudaGetSymbolAddress((void**)&H, g_H);
    cudaGetSymbolAddress((void**)&A, g_A);
    cudaGetSymbolAddress((void**)&B, g_B);

    const int T = 256;
    auto blocks = [&](long long work) { return (int)((work + T - 1) / T); };
    const int nScanBlocks = (n + SCAN_B - 1) / SCAN_B;

    // ----- CSR build (per call; graph-replay safe) -----
    zero_deg_kernel<<<blocks(n), T>>>(n);
    deg_kernel<<<blocks(E), T>>>(dst, E);
    dinv_kernel<<<blocks(n), T>>>(n);
    scan1_kernel<<<nScanBlocks, SCAN_B>>>(n);
    scan2_kernel<<<1, 1>>>(nScanBlocks);
    scan3_kernel<<<blocks(n + 1), T>>>(n, E);
    scatter_kernel<<<blocks(E), T>>>(src, dst, E);

    // ----- layer 1: 128 -> 128, relu -----
    {
        dim3 grid(128 / 128, (n + 127) / 128);
        gemm_kernel<128, 128, 16, 8, 8><<<grid, 256>>>(x, W1, H, n, 128, 128);
    }
    agg_gather_kernel<128, true, false>
        <<<blocks((long long)n * 32), T>>>(A, H, b1, n);

    // ----- layer 2: 128 -> 64 -----
    {
        dim3 grid(64 / 64, (n + 127) / 128);
        gemm_kernel<128, 64, 16, 8, 8><<<grid, 128>>>(A, W2, H, n, 128, 64);
    }
    agg_gather_kernel<64, false, false>
        <<<blocks((long long)n * 16), T>>>(B, H, b2, n);

    // ----- layer 3: 64 -> 16 + softmax -> d_out -----
    {
        dim3 grid(16 / 16, (n + 127) / 128);
        gemm_kernel<128, 16, 16, 8, 4><<<grid, 64>>>(B, W3, H, n, 64, 16);
    }
    agg_gather_kernel<16, false, true>
        <<<blocks((long long)n * 4), T>>>((float*)d_out, H, b3, n);
}

// round 5
// speedup vs baseline: 2.7134x; 1.0603x over previous
#include <cuda_runtime.h>
#include <cstdint>

// ---------------------------------------------------------------------------
// ExtendedGCN: 3-layer GCN (PyG GCNConv) + softmax.
//   Pull-based (atomic-free) aggregation over per-call CSR-by-dst with packed
//   (src, norm) payload.  GEMMs for layers 1/2 on tensor cores via
//   mma.sync.m16n8k8.tf32 with split-tf32 3-product emulation (fp32 accuracy).
//   relu fused into layer1 agg; softmax fused into layer3 agg.
// edge_index is int32 on device (JAX x64 disabled).
// ---------------------------------------------------------------------------

#define NMAX 50000
#define EMAX 800000
#define SCAN_B 1024

__device__ float  g_H[(size_t)NMAX * 128];
__device__ float  g_A[(size_t)NMAX * 128];
__device__ float  g_B[(size_t)NMAX * 64];
__device__ float  g_dinv[NMAX];
__device__ int    g_deg[NMAX];
__device__ int    g_offs[NMAX + 1];
__device__ int    g_cursor[NMAX];
__device__ float2 g_csr[EMAX];               // (src as int bits, norm)
__device__ int    g_bsum[(NMAX + SCAN_B - 1) / SCAN_B];
__device__ int    g_bpre[(NMAX + SCAN_B - 1) / SCAN_B];

// ----------------------------- CSR build ----------------------------------

__global__ void zero_deg_kernel(int n) {
    int i = blockIdx.x * blockDim.x + threadIdx.x;
    if (i < n) g_deg[i] = 0;
}

__global__ void deg_kernel(const int* __restrict__ dst, int E) {
    int e = blockIdx.x * blockDim.x + threadIdx.x;
    if (e < E) atomicAdd(&g_deg[dst[e]], 1);
}

// warp-shuffle block scan of deg -> offs (exclusive), totals -> g_bsum.
// Also computes dinv (fused).
__global__ void scan1_kernel(int n) {
    __shared__ int warp_tot[32];
    int tid = threadIdx.x;
    int lane = tid & 31;
    int warp = tid >> 5;
    int gid = blockIdx.x * SCAN_B + tid;
    int v = (gid < n) ? g_deg[gid] : 0;
    if (gid < n) g_dinv[gid] = rsqrtf((float)(v + 1));

    int inc = v;
#pragma unroll
    for (int o = 1; o < 32; o <<= 1) {
        int t = __shfl_up_sync(0xFFFFFFFFu, inc, o);
        if (lane >= o) inc += t;
    }
    if (lane == 31) warp_tot[warp] = inc;
    __syncthreads();
    if (warp == 0) {
        int w = warp_tot[lane];
        int wi = w;
#pragma unroll
        for (int o = 1; o < 32; o <<= 1) {
            int t = __shfl_up_sync(0xFFFFFFFFu, wi, o);
            if (lane >= o) wi += t;
        }
        warp_tot[lane] = wi - w;
        if (lane == 31) g_bsum[blockIdx.x] = wi;
    }
    __syncthreads();
    if (gid < n) g_offs[gid] = inc - v + warp_tot[warp];
}

__global__ void scan2_kernel(int nblocks) {
    if (threadIdx.x == 0 && blockIdx.x == 0) {
        int acc = 0;
        for (int b = 0; b < nblocks; b++) {
            g_bpre[b] = acc;
            acc += g_bsum[b];
        }
    }
}

__global__ void scan3_kernel(int n, int E) {
    int gid = blockIdx.x * blockDim.x + threadIdx.x;
    if (gid < n) {
        int o = g_offs[gid] + g_bpre[gid / SCAN_B];
        g_offs[gid] = o;
        g_cursor[gid] = o;
    }
    if (gid == n) g_offs[n] = E;
}

__global__ void scatter_kernel(const int* __restrict__ src,
                               const int* __restrict__ dst, int E) {
    int e = blockIdx.x * blockDim.x + threadIdx.x;
    if (e < E) {
        int s = src[e], d = dst[e];
        int pos = atomicAdd(&g_cursor[d], 1);
        float nrm = g_dinv[s] * g_dinv[d];
        g_csr[pos] = make_float2(__int_as_float(s), nrm);
    }
}

// ------------------------- tf32 tensor GEMM --------------------------------
// C[M,N] = A[M,K] @ W[K,N], split-tf32 emulation (3 mma products).
// BM=128, BK=16, 256 threads (8 warps as 4x2), warp tile 32 x (BN/2).

__device__ __forceinline__ uint32_t f2tf32(float x) {
    uint32_t r;
    asm("cvt.rna.tf32.f32 %0, %1;" : "=r"(r) : "f"(x));
    return r;
}

__device__ __forceinline__ void mma_tf32(float* c, const uint32_t* a,
                                         uint32_t b0, uint32_t b1) {
    asm volatile(
        "mma.sync.aligned.m16n8k8.row.col.f32.tf32.tf32.f32 "
        "{%0,%1,%2,%3}, {%4,%5,%6,%7}, {%8,%9}, {%0,%1,%2,%3};\n"
        : "+f"(c[0]), "+f"(c[1]), "+f"(c[2]), "+f"(c[3])
        : "r"(a[0]), "r"(a[1]), "r"(a[2]), "r"(a[3]), "r"(b0), "r"(b1));
}

template <int BN>
__global__ void gemm_tf32_kernel(const float* __restrict__ A,
                                 const float* __restrict__ W,
                                 float* __restrict__ C, int M, int K, int N) {
    constexpr int BM = 128, BK = 16, THREADS = 256;
    constexpr int AS = BK + 4;        // A smem stride (20) -> conflict-free frags
    constexpr int WS = BN + 4;        // W smem stride -> conflict-free frags
    constexpr int NF = BN / 16;       // n-frags per warp (warp covers BN/2 cols)

    __shared__ float As[2][BM * AS];  // [big/res][row*AS + k]
    __shared__ float Ws[2][BK * WS];  // [big/res][k*WS + col]

    const int tid = threadIdx.x;
    const int lane = tid & 31;
    const int warp = tid >> 5;
    const int g = lane >> 2;          // groupID
    const int tg = lane & 3;          // thread-in-group
    const int wrb = (warp & 3) * 32;  // warp row base (4 warps in M)
    const int wcb = (warp >> 2) * (BN / 2);  // warp col base (2 warps in N)
    const int brow = blockIdx.y * BM;
    const int bcol = blockIdx.x * BN;

    float c[2][NF][4];
#pragma unroll
    for (int mi = 0; mi < 2; mi++)
#pragma unroll
        for (int ni = 0; ni < NF; ni++)
#pragma unroll
            for (int j = 0; j < 4; j++) c[mi][ni][j] = 0.0f;

    for (int k0 = 0; k0 < K; k0 += BK) {
        // stage A tile (BM x BK), split into big + residual tf32
#pragma unroll
        for (int p = tid; p < BM * BK / 4; p += THREADS) {
            int r = p / (BK / 4);
            int cc = (p % (BK / 4)) * 4;
            int gr = brow + r;
            float4 v = (gr < M) ? *(const float4*)&A[(size_t)gr * K + k0 + cc]
                                : make_float4(0.f, 0.f, 0.f, 0.f);
            const float vv[4] = {v.x, v.y, v.z, v.w};
#pragma unroll
            for (int j = 0; j < 4; j++) {
                uint32_t big = f2tf32(vv[j]);
                float res = vv[j] - __uint_as_float(big);
                As[0][r * AS + cc + j] = __uint_as_float(big);
                As[1][r * AS + cc + j] = __uint_as_float(f2tf32(res));
            }
        }
        // stage W tile (BK x BN)
#pragma unroll
        for (int p = tid; p < BK * BN / 4; p += THREADS) {
            int r = p / (BN / 4);
            int cc = (p % (BN / 4)) * 4;
            float4 v = *(const float4*)&W[(size_t)(k0 + r) * N + bcol + cc];
            const float vv[4] = {v.x, v.y, v.z, v.w};
#pragma unroll
            for (int j = 0; j < 4; j++) {
                uint32_t big = f2tf32(vv[j]);
                float res = vv[j] - __uint_as_float(big);
                Ws[0][r * WS + cc + j] = __uint_as_float(big);
                Ws[1][r * WS + cc + j] = __uint_as_float(f2tf32(res));
            }
        }
        __syncthreads();

#pragma unroll
        for (int ks = 0; ks < BK / 8; ks++) {
            const int kb = ks * 8;
            uint32_t Ab[2][4], Ar[2][4];
#pragma unroll
            for (int mi = 0; mi < 2; mi++) {
                int r0 = wrb + mi * 16 + g;
                Ab[mi][0] = __float_as_uint(As[0][r0 * AS + kb + tg]);
                Ab[mi][1] = __float_as_uint(As[0][(r0 + 8) * AS + kb + tg]);
                Ab[mi][2] = __float_as_uint(As[0][r0 * AS + kb + tg + 4]);
                Ab[mi][3] = __float_as_uint(As[0][(r0 + 8) * AS + kb + tg + 4]);
                Ar[mi][0] = __float_as_uint(As[1][r0 * AS + kb + tg]);
                Ar[mi][1] = __float_as_uint(As[1][(r0 + 8) * AS + kb + tg]);
                Ar[mi][2] = __float_as_uint(As[1][r0 * AS + kb + tg + 4]);
                Ar[mi][3] = __float_as_uint(As[1][(r0 + 8) * AS + kb + tg + 4]);
            }
#pragma unroll
            for (int ni = 0; ni < NF; ni++) {
                int col = wcb + ni * 8 + g;
                uint32_t Bb0 = __float_as_uint(Ws[0][(kb + tg) * WS + col]);
                uint32_t Bb1 = __float_as_uint(Ws[0][(kb + tg + 4) * WS + col]);
                uint32_t Br0 = __float_as_uint(Ws[1][(kb + tg) * WS + col]);
                uint32_t Br1 = __float_as_uint(Ws[1][(kb + tg + 4) * WS + col]);
#pragma unroll
                for (int mi = 0; mi < 2; mi++) {
                    mma_tf32(c[mi][ni], Ab[mi], Bb0, Bb1);  // big*big
                    mma_tf32(c[mi][ni], Ar[mi], Bb0, Bb1);  // res*big
                    mma_tf32(c[mi][ni], Ab[mi], Br0, Br1);  // big*res
                }
            }
        }
        __syncthreads();
    }

    // epilogue
#pragma unroll
    for (int mi = 0; mi < 2; mi++) {
        int gr0 = brow + wrb + mi * 16 + g;
        int gr1 = gr0 + 8;
#pragma unroll
        for (int ni = 0; ni < NF; ni++) {
            int gc = bcol + wcb + ni * 8 + 2 * tg;
            if (gr0 < M)
                *(float2*)&C[(size_t)gr0 * N + gc] =
                    make_float2(c[mi][ni][0], c[mi][ni][1]);
            if (gr1 < M)
                *(float2*)&C[(size_t)gr1 * N + gc] =
                    make_float2(c[mi][ni][2], c[mi][ni][3]);
        }
    }
}

// --------------------------- SIMT GEMM (layer 3) ---------------------------

template <int BM, int BN, int BK, int TM, int TN>
__global__ void gemm_kernel(const float* __restrict__ A,
                            const float* __restrict__ W,
                            float* __restrict__ C, int M, int K, int N) {
    constexpr int THREADS = (BM / TM) * (BN / TN);
    __shared__ float As[BK][BM];
    __shared__ float Ws[BK][BN];

    const int block_row = blockIdx.y * BM;
    const int block_col = blockIdx.x * BN;
    const int tid = threadIdx.x;
    const int tx = tid % (BN / TN);
    const int ty = tid / (BN / TN);

    constexpr int A_F4_PER_ROW = BK / 4;
    const int a_row0 = tid / A_F4_PER_ROW;
    const int a_col = (tid % A_F4_PER_ROW) * 4;
    constexpr int A_ROW_STRIDE = THREADS / A_F4_PER_ROW;

    constexpr int W_F4_PER_ROW = BN / 4;
    const int w_row0 = tid / W_F4_PER_ROW;
    const int w_col = (tid % W_F4_PER_ROW) * 4;
    constexpr int W_ROW_STRIDE = THREADS / W_F4_PER_ROW;

    float acc[TM][TN];
#pragma unroll
    for (int i = 0; i < TM; i++)
#pragma unroll
        for (int j = 0; j < TN; j++) acc[i][j] = 0.0f;

    for (int k0 = 0; k0 < K; k0 += BK) {
#pragma unroll
        for (int r = a_row0; r < BM; r += A_ROW_STRIDE) {
            int gr = block_row + r;
            float4 v = (gr < M)
                ? *(const float4*)&A[(size_t)gr * K + k0 + a_col]
                : make_float4(0.f, 0.f, 0.f, 0.f);
            As[a_col + 0][r] = v.x;
            As[a_col + 1][r] = v.y;
            As[a_col + 2][r] = v.z;
            As[a_col + 3][r] = v.w;
        }
#pragma unroll
        for (int r = w_row0; r < BK; r += W_ROW_STRIDE) {
            *(float4*)&Ws[r][w_col] =
                *(const float4*)&W[(size_t)(k0 + r) * N + block_col + w_col];
        }
        __syncthreads();

#pragma unroll
        for (int k = 0; k < BK; k++) {
            float ra[TM], rb[TN];
#pragma unroll
            for (int i = 0; i < TM; i += 4)
                *(float4*)&ra[i] = *(const float4*)&As[k][ty * TM + i];
#pragma unroll
            for (int j = 0; j < TN; j += 4)
                *(float4*)&rb[j] = *(const float4*)&Ws[k][tx * TN + j];
#pragma unroll
            for (int i = 0; i < TM; i++)
#pragma unroll
                for (int j = 0; j < TN; j++) acc[i][j] += ra[i] * rb[j];
        }
        __syncthreads();
    }

#pragma unroll
    for (int i = 0; i < TM; i++) {
        int gr = block_row + ty * TM + i;
        if (gr < M) {
#pragma unroll
            for (int j = 0; j < TN; j += 4)
                *(float4*)&C[(size_t)gr * N + block_col + tx * TN + j] =
                    *(float4*)&acc[i][j];
        }
    }
}

// ------------------------ gather aggregation ------------------------------

template <int D, bool RELU, bool SOFTMAX>
__global__ void agg_gather_kernel(float* __restrict__ out,
                                  const float* __restrict__ H,
                                  const float* __restrict__ b, int n) {
    constexpr int LPN = D / 4;
    constexpr int NPW = 32 / LPN;
    int warp = (blockIdx.x * blockDim.x + threadIdx.x) >> 5;
    int lane = threadIdx.x & 31;
    int grp = lane / LPN;
    int f = lane % LPN;
    int i = warp * NPW + grp;
    if (i >= n) return;

    float di = g_dinv[i];
    float s2 = di * di;
    float4 h = ((const float4*)H)[(size_t)i * LPN + f];
    float4 bb = ((const float4*)b)[f];
    float4 acc;
    acc.x = bb.x + s2 * h.x;
    acc.y = bb.y + s2 * h.y;
    acc.z = bb.z + s2 * h.z;
    acc.w = bb.w + s2 * h.w;

    int beg = g_offs[i], end = g_offs[i + 1];
#pragma unroll 4
    for (int e = beg; e < end; e++) {
        float2 p = __ldg(&g_csr[e]);
        int s = __float_as_int(p.x);
        float nrm = p.y;
        float4 v = ((const float4*)H)[(size_t)s * LPN + f];
        acc.x += nrm * v.x;
        acc.y += nrm * v.y;
        acc.z += nrm * v.z;
        acc.w += nrm * v.w;
    }

    if (RELU) {
        acc.x = fmaxf(acc.x, 0.0f);
        acc.y = fmaxf(acc.y, 0.0f);
        acc.z = fmaxf(acc.z, 0.0f);
        acc.w = fmaxf(acc.w, 0.0f);
    }

    if (SOFTMAX) {
        float m = fmaxf(fmaxf(acc.x, acc.y), fmaxf(acc.z, acc.w));
#pragma unroll
        for (int o = 1; o < LPN; o <<= 1)
            m = fmaxf(m, __shfl_xor_sync(0xFFFFFFFFu, m, o, LPN));
        acc.x = __expf(acc.x - m);
        acc.y = __expf(acc.y - m);
        acc.z = __expf(acc.z - m);
        acc.w = __expf(acc.w - m);
        float s = acc.x + acc.y + acc.z + acc.w;
#pragma unroll
        for (int o = 1; o < LPN; o <<= 1)
            s += __shfl_xor_sync(0xFFFFFFFFu, s, o, LPN);
        float inv = 1.0f / s;
        acc.x *= inv;
        acc.y *= inv;
        acc.z *= inv;
        acc.w *= inv;
    }

    ((float4*)out)[(size_t)i * LPN + f] = acc;
}

// ------------------------------- launch -----------------------------------

extern "C" void kernel_launch(void* const* d_in, const int* in_sizes, int n_in,
                              void* d_out, int out_size) {
    const float* x  = (const float*)d_in[0];
    const int*   ei = (const int*)d_in[1];   // int32 (JAX x64 disabled)
    const float* W1 = (const float*)d_in[2];
    const float* b1 = (const float*)d_in[3];
    const float* W2 = (const float*)d_in[4];
    const float* b2 = (const float*)d_in[5];
    const float* W3 = (const float*)d_in[6];
    const float* b3 = (const float*)d_in[7];

    const int n = in_sizes[0] / 128;
    const int E = in_sizes[1] / 2;
    const int* src = ei;
    const int* dst = ei + E;

    float *H, *A, *B;
    cudaGetSymbolAddress((void**)&H, g_H);
    cudaGetSymbolAddress((void**)&A, g_A);
    cudaGetSymbolAddress((void**)&B, g_B);

    const int T = 256;
    auto blocks = [&](long long work) { return (int)((work + T - 1) / T); };
    const int nScanBlocks = (n + SCAN_B - 1) / SCAN_B;

    // ----- CSR build (per call; graph-replay safe) -----
    zero_deg_kernel<<<blocks(n), T>>>(n);
    deg_kernel<<<blocks(E), T>>>(dst, E);
    scan1_kernel<<<nScanBlocks, SCAN_B>>>(n);
    scan2_kernel<<<1, 1>>>(nScanBlocks);
    scan3_kernel<<<blocks(n + 1), T>>>(n, E);
    scatter_kernel<<<blocks(E), T>>>(src, dst, E);

    const int gy = (n + 127) / 128;

    // ----- layer 1: 128 -> 128 (tf32 TC), relu fused in agg -----
    gemm_tf32_kernel<128><<<dim3(1, gy), 256>>>(x, W1, H, n, 128, 128);
    agg_gather_kernel<128, true, false>
        <<<blocks((long long)n * 32), T>>>(A, H, b1, n);

    // ----- layer 2: 128 -> 64 (tf32 TC) -----
    gemm_tf32_kernel<64><<<dim3(1, gy), 256>>>(A, W2, H, n, 128, 64);
    agg_gather_kernel<64, false, false>
        <<<blocks((long long)n * 16), T>>>(B, H, b2, n);

    // ----- layer 3: 64 -> 16 (SIMT) + softmax -> d_out -----
    gemm_kernel<128, 16, 16, 8, 4><<<dim3(1, gy), 64>>>(B, W3, H, n, 64, 16);
    agg_gather_kernel<16, false, true>
        <<<blocks((long long)n * 4), T>>>((float*)d_out, H, b3, n);
}

// round 6
// speedup vs baseline: 3.0457x; 1.1225x over previous
#include <cuda_runtime.h>
#include <cstdint>

// ---------------------------------------------------------------------------
// ExtendedGCN: 3-layer GCN (PyG GCNConv) + softmax.
//   Pull-based (atomic-free) aggregation over per-call CSR-by-dst with packed
//   (src, norm) payload.  Layers 1/2 GEMM on tensor cores via
//   mma.sync.m16n8k8.tf32 with split-tf32 3-product emulation (fp32 accuracy).
//   relu fused into layer1 agg; softmax fused into layer3 agg.
//   CSR build overlapped with layer-1 GEMM on a second stream.
// edge_index is int32 on device (JAX x64 disabled).
// ---------------------------------------------------------------------------

#define NMAX 50000
#define EMAX 800000
#define SCAN_B 1024
#define NSCANB ((NMAX + SCAN_B - 1) / SCAN_B)

__device__ float  g_H[(size_t)NMAX * 128];
__device__ float  g_A[(size_t)NMAX * 128];
__device__ float  g_B[(size_t)NMAX * 64];
__device__ float  g_dinv[NMAX];
__device__ int    g_deg[NMAX];
__device__ int    g_offs[NMAX + 1];
__device__ int    g_cursor[NMAX];
__device__ float2 g_csr[EMAX];               // (src as int bits, norm)
__device__ int    g_bsum[NSCANB];

// ----------------------------- CSR build ----------------------------------

__global__ void deg_kernel(const int* __restrict__ dst, int E) {
    int e = blockIdx.x * blockDim.x + threadIdx.x;
    if (e < E) atomicAdd(&g_deg[dst[e]], 1);
}

// warp-shuffle block scan of deg -> offs (exclusive within block),
// block totals -> g_bsum; dinv fused.
__global__ void scan1_kernel(int n) {
    __shared__ int warp_tot[32];
    int tid = threadIdx.x;
    int lane = tid & 31;
    int warp = tid >> 5;
    int gid = blockIdx.x * SCAN_B + tid;
    int v = (gid < n) ? g_deg[gid] : 0;
    if (gid < n) g_dinv[gid] = rsqrtf((float)(v + 1));

    int inc = v;
#pragma unroll
    for (int o = 1; o < 32; o <<= 1) {
        int t = __shfl_up_sync(0xFFFFFFFFu, inc, o);
        if (lane >= o) inc += t;
    }
    if (lane == 31) warp_tot[warp] = inc;
    __syncthreads();
    if (warp == 0) {
        int w = warp_tot[lane];
        int wi = w;
#pragma unroll
        for (int o = 1; o < 32; o <<= 1) {
            int t = __shfl_up_sync(0xFFFFFFFFu, wi, o);
            if (lane >= o) wi += t;
        }
        warp_tot[lane] = wi - w;
        if (lane == 31) g_bsum[blockIdx.x] = wi;
    }
    __syncthreads();
    if (gid < n) g_offs[gid] = inc - v + warp_tot[warp];
}

// add cross-block prefix (computed inline from <=NSCANB totals), init cursor
__global__ void scan3_kernel(int n, int E, int nblocks) {
    int gid = blockIdx.x * blockDim.x + threadIdx.x;
    if (gid < n) {
        int nb = gid / SCAN_B;
        int acc = 0;
        for (int j = 0; j < nb; j++) acc += g_bsum[j];  // L1-broadcast hits
        int o = g_offs[gid] + acc;
        g_offs[gid] = o;
        g_cursor[gid] = o;
    }
    if (gid == n) g_offs[n] = E;
}

__global__ void scatter_kernel(const int* __restrict__ src,
                               const int* __restrict__ dst, int E) {
    int e = blockIdx.x * blockDim.x + threadIdx.x;
    if (e < E) {
        int s = src[e], d = dst[e];
        int pos = atomicAdd(&g_cursor[d], 1);
        float nrm = g_dinv[s] * g_dinv[d];
        g_csr[pos] = make_float2(__int_as_float(s), nrm);
    }
}

// ------------------------- tf32 tensor GEMM --------------------------------

__device__ __forceinline__ uint32_t f2tf32(float x) {
    uint32_t r;
    asm("cvt.rna.tf32.f32 %0, %1;" : "=r"(r) : "f"(x));
    return r;
}

__device__ __forceinline__ void mma_tf32(float* c, const uint32_t* a,
                                         uint32_t b0, uint32_t b1) {
    asm volatile(
        "mma.sync.aligned.m16n8k8.row.col.f32.tf32.tf32.f32 "
        "{%0,%1,%2,%3}, {%4,%5,%6,%7}, {%8,%9}, {%0,%1,%2,%3};\n"
        : "+f"(c[0]), "+f"(c[1]), "+f"(c[2]), "+f"(c[3])
        : "r"(a[0]), "r"(a[1]), "r"(a[2]), "r"(a[3]), "r"(b0), "r"(b1));
}

template <int BN>
__global__ void gemm_tf32_kernel(const float* __restrict__ A,
                                 const float* __restrict__ W,
                                 float* __restrict__ C, int M, int K, int N) {
    constexpr int BM = 128, BK = 16, THREADS = 256;
    constexpr int AS = BK + 4;
    constexpr int WS = BN + 4;
    constexpr int NF = BN / 16;

    __shared__ float As[2][BM * AS];
    __shared__ float Ws[2][BK * WS];

    const int tid = threadIdx.x;
    const int lane = tid & 31;
    const int warp = tid >> 5;
    const int g = lane >> 2;
    const int tg = lane & 3;
    const int wrb = (warp & 3) * 32;
    const int wcb = (warp >> 2) * (BN / 2);
    const int brow = blockIdx.y * BM;
    const int bcol = blockIdx.x * BN;

    float c[2][NF][4];
#pragma unroll
    for (int mi = 0; mi < 2; mi++)
#pragma unroll
        for (int ni = 0; ni < NF; ni++)
#pragma unroll
            for (int j = 0; j < 4; j++) c[mi][ni][j] = 0.0f;

    for (int k0 = 0; k0 < K; k0 += BK) {
#pragma unroll
        for (int p = tid; p < BM * BK / 4; p += THREADS) {
            int r = p / (BK / 4);
            int cc = (p % (BK / 4)) * 4;
            int gr = brow + r;
            float4 v = (gr < M) ? *(const float4*)&A[(size_t)gr * K + k0 + cc]
                                : make_float4(0.f, 0.f, 0.f, 0.f);
            const float vv[4] = {v.x, v.y, v.z, v.w};
#pragma unroll
            for (int j = 0; j < 4; j++) {
                uint32_t big = f2tf32(vv[j]);
                float res = vv[j] - __uint_as_float(big);
                As[0][r * AS + cc + j] = __uint_as_float(big);
                As[1][r * AS + cc + j] = __uint_as_float(f2tf32(res));
            }
        }
#pragma unroll
        for (int p = tid; p < BK * BN / 4; p += THREADS) {
            int r = p / (BN / 4);
            int cc = (p % (BN / 4)) * 4;
            float4 v = *(const float4*)&W[(size_t)(k0 + r) * N + bcol + cc];
            const float vv[4] = {v.x, v.y, v.z, v.w};
#pragma unroll
            for (int j = 0; j < 4; j++) {
                uint32_t big = f2tf32(vv[j]);
                float res = vv[j] - __uint_as_float(big);
                Ws[0][r * WS + cc + j] = __uint_as_float(big);
                Ws[1][r * WS + cc + j] = __uint_as_float(f2tf32(res));
            }
        }
        __syncthreads();

#pragma unroll
        for (int ks = 0; ks < BK / 8; ks++) {
            const int kb = ks * 8;
            uint32_t Ab[2][4], Ar[2][4];
#pragma unroll
            for (int mi = 0; mi < 2; mi++) {
                int r0 = wrb + mi * 16 + g;
                Ab[mi][0] = __float_as_uint(As[0][r0 * AS + kb + tg]);
                Ab[mi][1] = __float_as_uint(As[0][(r0 + 8) * AS + kb + tg]);
                Ab[mi][2] = __float_as_uint(As[0][r0 * AS + kb + tg + 4]);
                Ab[mi][3] = __float_as_uint(As[0][(r0 + 8) * AS + kb + tg + 4]);
                Ar[mi][0] = __float_as_uint(As[1][r0 * AS + kb + tg]);
                Ar[mi][1] = __float_as_uint(As[1][(r0 + 8) * AS + kb + tg]);
                Ar[mi][2] = __float_as_uint(As[1][r0 * AS + kb + tg + 4]);
                Ar[mi][3] = __float_as_uint(As[1][(r0 + 8) * AS + kb + tg + 4]);
            }
#pragma unroll
            for (int ni = 0; ni < NF; ni++) {
                int col = wcb + ni * 8 + g;
                uint32_t Bb0 = __float_as_uint(Ws[0][(kb + tg) * WS + col]);
                uint32_t Bb1 = __float_as_uint(Ws[0][(kb + tg + 4) * WS + col]);
                uint32_t Br0 = __float_as_uint(Ws[1][(kb + tg) * WS + col]);
                uint32_t Br1 = __float_as_uint(Ws[1][(kb + tg + 4) * WS + col]);
#pragma unroll
                for (int mi = 0; mi < 2; mi++) {
                    mma_tf32(c[mi][ni], Ab[mi], Bb0, Bb1);
                    mma_tf32(c[mi][ni], Ar[mi], Bb0, Bb1);
                    mma_tf32(c[mi][ni], Ab[mi], Br0, Br1);
                }
            }
        }
        __syncthreads();
    }

#pragma unroll
    for (int mi = 0; mi < 2; mi++) {
        int gr0 = brow + wrb + mi * 16 + g;
        int gr1 = gr0 + 8;
#pragma unroll
        for (int ni = 0; ni < NF; ni++) {
            int gc = bcol + wcb + ni * 8 + 2 * tg;
            if (gr0 < M)
                *(float2*)&C[(size_t)gr0 * N + gc] =
                    make_float2(c[mi][ni][0], c[mi][ni][1]);
            if (gr1 < M)
                *(float2*)&C[(size_t)gr1 * N + gc] =
                    make_float2(c[mi][ni][2], c[mi][ni][3]);
        }
    }
}

// --------------------------- SIMT GEMM (layer 3) ---------------------------

template <int BM, int BN, int BK, int TM, int TN>
__global__ void gemm_kernel(const float* __restrict__ A,
                            const float* __restrict__ W,
                            float* __restrict__ C, int M, int K, int N) {
    constexpr int THREADS = (BM / TM) * (BN / TN);
    __shared__ float As[BK][BM];
    __shared__ float Ws[BK][BN];

    const int block_row = blockIdx.y * BM;
    const int block_col = blockIdx.x * BN;
    const int tid = threadIdx.x;
    const int tx = tid % (BN / TN);
    const int ty = tid / (BN / TN);

    constexpr int A_F4_PER_ROW = BK / 4;
    const int a_row0 = tid / A_F4_PER_ROW;
    const int a_col = (tid % A_F4_PER_ROW) * 4;
    constexpr int A_ROW_STRIDE = THREADS / A_F4_PER_ROW;

    constexpr int W_F4_PER_ROW = BN / 4;
    const int w_row0 = tid / W_F4_PER_ROW;
    const int w_col = (tid % W_F4_PER_ROW) * 4;
    constexpr int W_ROW_STRIDE = THREADS / W_F4_PER_ROW;

    float acc[TM][TN];
#pragma unroll
    for (int i = 0; i < TM; i++)
#pragma unroll
        for (int j = 0; j < TN; j++) acc[i][j] = 0.0f;

    for (int k0 = 0; k0 < K; k0 += BK) {
#pragma unroll
        for (int r = a_row0; r < BM; r += A_ROW_STRIDE) {
            int gr = block_row + r;
            float4 v = (gr < M)
                ? *(const float4*)&A[(size_t)gr * K + k0 + a_col]
                : make_float4(0.f, 0.f, 0.f, 0.f);
            As[a_col + 0][r] = v.x;
            As[a_col + 1][r] = v.y;
            As[a_col + 2][r] = v.z;
            As[a_col + 3][r] = v.w;
        }
#pragma unroll
        for (int r = w_row0; r < BK; r += W_ROW_STRIDE) {
            *(float4*)&Ws[r][w_col] =
                *(const float4*)&W[(size_t)(k0 + r) * N + block_col + w_col];
        }
        __syncthreads();

#pragma unroll
        for (int k = 0; k < BK; k++) {
            float ra[TM], rb[TN];
#pragma unroll
            for (int i = 0; i < TM; i += 4)
                *(float4*)&ra[i] = *(const float4*)&As[k][ty * TM + i];
#pragma unroll
            for (int j = 0; j < TN; j += 4)
                *(float4*)&rb[j] = *(const float4*)&Ws[k][tx * TN + j];
#pragma unroll
            for (int i = 0; i < TM; i++)
#pragma unroll
                for (int j = 0; j < TN; j++) acc[i][j] += ra[i] * rb[j];
        }
        __syncthreads();
    }

#pragma unroll
    for (int i = 0; i < TM; i++) {
        int gr = block_row + ty * TM + i;
        if (gr < M) {
#pragma unroll
            for (int j = 0; j < TN; j += 4)
                *(float4*)&C[(size_t)gr * N + block_col + tx * TN + j] =
                    *(float4*)&acc[i][j];
        }
    }
}

// ------------------------ gather aggregation ------------------------------

template <int D, bool RELU, bool SOFTMAX>
__global__ void agg_gather_kernel(float* __restrict__ out,
                                  const float* __restrict__ H,
                                  const float* __restrict__ b, int n) {
    constexpr int LPN = D / 4;
    constexpr int NPW = 32 / LPN;
    int warp = (blockIdx.x * blockDim.x + threadIdx.x) >> 5;
    int lane = threadIdx.x & 31;
    int grp = lane / LPN;
    int f = lane % LPN;
    int i = warp * NPW + grp;
    if (i >= n) return;

    float di = g_dinv[i];
    float s2 = di * di;
    float4 h = ((const float4*)H)[(size_t)i * LPN + f];
    float4 bb = ((const float4*)b)[f];
    float4 acc;
    acc.x = bb.x + s2 * h.x;
    acc.y = bb.y + s2 * h.y;
    acc.z = bb.z + s2 * h.z;
    acc.w = bb.w + s2 * h.w;

    int beg = g_offs[i], end = g_offs[i + 1];
#pragma unroll 4
    for (int e = beg; e < end; e++) {
        float2 p = __ldg(&g_csr[e]);
        int s = __float_as_int(p.x);
        float nrm = p.y;
        float4 v = ((const float4*)H)[(size_t)s * LPN + f];
        acc.x += nrm * v.x;
        acc.y += nrm * v.y;
        acc.z += nrm * v.z;
        acc.w += nrm * v.w;
    }

    if (RELU) {
        acc.x = fmaxf(acc.x, 0.0f);
        acc.y = fmaxf(acc.y, 0.0f);
        acc.z = fmaxf(acc.z, 0.0f);
        acc.w = fmaxf(acc.w, 0.0f);
    }

    if (SOFTMAX) {
        float m = fmaxf(fmaxf(acc.x, acc.y), fmaxf(acc.z, acc.w));
#pragma unroll
        for (int o = 1; o < LPN; o <<= 1)
            m = fmaxf(m, __shfl_xor_sync(0xFFFFFFFFu, m, o, LPN));
        acc.x = __expf(acc.x - m);
        acc.y = __expf(acc.y - m);
        acc.z = __expf(acc.z - m);
        acc.w = __expf(acc.w - m);
        float s = acc.x + acc.y + acc.z + acc.w;
#pragma unroll
        for (int o = 1; o < LPN; o <<= 1)
            s += __shfl_xor_sync(0xFFFFFFFFu, s, o, LPN);
        float inv = 1.0f / s;
        acc.x *= inv;
        acc.y *= inv;
        acc.z *= inv;
        acc.w *= inv;
    }

    ((float4*)out)[(size_t)i * LPN + f] = acc;
}

// ------------------------------- launch -----------------------------------

static cudaStream_t s_gemm = nullptr;
static cudaEvent_t  s_evFork = nullptr, s_evJoin = nullptr;

extern "C" void kernel_launch(void* const* d_in, const int* in_sizes, int n_in,
                              void* d_out, int out_size) {
    const float* x  = (const float*)d_in[0];
    const int*   ei = (const int*)d_in[1];   // int32 (JAX x64 disabled)
    const float* W1 = (const float*)d_in[2];
    const float* b1 = (const float*)d_in[3];
    const float* W2 = (const float*)d_in[4];
    const float* b2 = (const float*)d_in[5];
    const float* W3 = (const float*)d_in[6];
    const float* b3 = (const float*)d_in[7];

    const int n = in_sizes[0] / 128;
    const int E = in_sizes[1] / 2;
    const int* src = ei;
    const int* dst = ei + E;

    float *H, *A, *B;
    int* degp;
    cudaGetSymbolAddress((void**)&H, g_H);
    cudaGetSymbolAddress((void**)&A, g_A);
    cudaGetSymbolAddress((void**)&B, g_B);
    cudaGetSymbolAddress((void**)&degp, g_deg);

    if (s_gemm == nullptr) {
        cudaStreamCreateWithFlags(&s_gemm, cudaStreamNonBlocking);
        cudaEventCreateWithFlags(&s_evFork, cudaEventDisableTiming);
        cudaEventCreateWithFlags(&s_evJoin, cudaEventDisableTiming);
    }

    const int T = 256;
    auto blocks = [&](long long work) { return (int)((work + T - 1) / T); };
    const int nScanBlocks = (n + SCAN_B - 1) / SCAN_B;
    const int gy = (n + 127) / 128;

    // Fork: layer-1 GEMM (independent of CSR) on side stream.
    cudaEventRecord(s_evFork, 0);
    cudaStreamWaitEvent(s_gemm, s_evFork, 0);
    gemm_tf32_kernel<128><<<dim3(1, gy), 256, 0, s_gemm>>>(x, W1, H, n, 128, 128);
    cudaEventRecord(s_evJoin, s_gemm);

    // CSR build on main stream (concurrent with GEMM1).
    cudaMemsetAsync(degp, 0, (size_t)n * sizeof(int), 0);
    deg_kernel<<<blocks(E), T>>>(dst, E);
    scan1_kernel<<<nScanBlocks, SCAN_B>>>(n);
    scan3_kernel<<<blocks(n + 1), T>>>(n, E, nScanBlocks);
    scatter_kernel<<<blocks(E), T>>>(src, dst, E);

    // Join: gather1 needs both CSR and H.
    cudaStreamWaitEvent(0, s_evJoin, 0);

    // ----- layer 1 aggregation (relu fused) -----
    agg_gather_kernel<128, true, false>
        <<<blocks((long long)n * 32), T>>>(A, H, b1, n);

    // ----- layer 2: 128 -> 64 (tf32 TC) -----
    gemm_tf32_kernel<64><<<dim3(1, gy), 256>>>(A, W2, H, n, 128, 64);
    agg_gather_kernel<64, false, false>
        <<<blocks((long long)n * 16), T>>>(B, H, b2, n);

    // ----- layer 3: 64 -> 16 (SIMT, 128 thr) + softmax -> d_out -----
    gemm_kernel<128, 16, 16, 4, 4><<<dim3(1, gy), 128>>>(B, W3, H, n, 64, 16);
    agg_gather_kernel<16, false, true>
        <<<blocks((long long)n * 4), T>>>((float*)d_out, H, b3, n);
}

// round 7
// speedup vs baseline: 3.2460x; 1.0658x over previous
#include <cuda_runtime.h>
#include <cuda_fp16.h>
#include <cstdint>

// ---------------------------------------------------------------------------
// ExtendedGCN: 3-layer GCN (PyG GCNConv) + softmax.
//   Pull-based (atomic-free) aggregation over per-call CSR-by-dst with packed
//   (src, norm) payload.  Layers 1/2 GEMM on tensor cores (split-tf32, fp32
//   accuracy); H intermediates stored fp16 to halve gather traffic, fp32
//   accumulation.  Layer 3 fully fp32.  relu fused into agg1; softmax into
//   agg3.  CSR build overlapped with layer-1 GEMM on a second stream.
// edge_index is int32 on device (JAX x64 disabled).
// ---------------------------------------------------------------------------

#define NMAX 50000
#define EMAX 800000
#define SCAN_B 1024
#define NSCANB ((NMAX + SCAN_B - 1) / SCAN_B)

__device__ __half g_H16[(size_t)NMAX * 128];  // fp16 GEMM outputs (layers 1/2)
__device__ float  g_H[(size_t)NMAX * 64];     // fp32 layer-3 GEMM output
__device__ float  g_A[(size_t)NMAX * 128];    // agg outputs (ping)
__device__ float  g_B[(size_t)NMAX * 64];     // agg outputs (pong)
__device__ float  g_dinv[NMAX];
__device__ int    g_deg[NMAX];
__device__ int    g_offs[NMAX + 1];
__device__ int    g_cursor[NMAX];
__device__ float2 g_csr[EMAX];                // (src as int bits, norm)
__device__ int    g_bsum[NSCANB];

// ----------------------------- CSR build ----------------------------------

__global__ void deg_kernel(const int* __restrict__ dst, int E) {
    int e = blockIdx.x * blockDim.x + threadIdx.x;
    if (e < E) atomicAdd(&g_deg[dst[e]], 1);
}

__global__ void scan1_kernel(int n) {
    __shared__ int warp_tot[32];
    int tid = threadIdx.x;
    int lane = tid & 31;
    int warp = tid >> 5;
    int gid = blockIdx.x * SCAN_B + tid;
    int v = (gid < n) ? g_deg[gid] : 0;
    if (gid < n) g_dinv[gid] = rsqrtf((float)(v + 1));

    int inc = v;
#pragma unroll
    for (int o = 1; o < 32; o <<= 1) {
        int t = __shfl_up_sync(0xFFFFFFFFu, inc, o);
        if (lane >= o) inc += t;
    }
    if (lane == 31) warp_tot[warp] = inc;
    __syncthreads();
    if (warp == 0) {
        int w = warp_tot[lane];
        int wi = w;
#pragma unroll
        for (int o = 1; o < 32; o <<= 1) {
            int t = __shfl_up_sync(0xFFFFFFFFu, wi, o);
            if (lane >= o) wi += t;
        }
        warp_tot[lane] = wi - w;
        if (lane == 31) g_bsum[blockIdx.x] = wi;
    }
    __syncthreads();
    if (gid < n) g_offs[gid] = inc - v + warp_tot[warp];
}

__global__ void scan3_kernel(int n, int E, int nblocks) {
    int gid = blockIdx.x * blockDim.x + threadIdx.x;
    if (gid < n) {
        int nb = gid / SCAN_B;
        int acc = 0;
#pragma unroll 8
        for (int j = 0; j < nb; j++) acc += __ldg(&g_bsum[j]);
        int o = g_offs[gid] + acc;
        g_offs[gid] = o;
        g_cursor[gid] = o;
    }
    if (gid == n) g_offs[n] = E;
}

__global__ void scatter_kernel(const int* __restrict__ src,
                               const int* __restrict__ dst, int E) {
    int e = blockIdx.x * blockDim.x + threadIdx.x;
    if (e < E) {
        int s = src[e], d = dst[e];
        int pos = atomicAdd(&g_cursor[d], 1);
        float nrm = g_dinv[s] * g_dinv[d];
        g_csr[pos] = make_float2(__int_as_float(s), nrm);
    }
}

// ------------------------- tf32 tensor GEMM --------------------------------

__device__ __forceinline__ uint32_t f2tf32(float x) {
    uint32_t r;
    asm("cvt.rna.tf32.f32 %0, %1;" : "=r"(r) : "f"(x));
    return r;
}

__device__ __forceinline__ void mma_tf32(float* c, const uint32_t* a,
                                         uint32_t b0, uint32_t b1) {
    asm volatile(
        "mma.sync.aligned.m16n8k8.row.col.f32.tf32.tf32.f32 "
        "{%0,%1,%2,%3}, {%4,%5,%6,%7}, {%8,%9}, {%0,%1,%2,%3};\n"
        : "+f"(c[0]), "+f"(c[1]), "+f"(c[2]), "+f"(c[3])
        : "r"(a[0]), "r"(a[1]), "r"(a[2]), "r"(a[3]), "r"(b0), "r"(b1));
}

// C stored fp16 (half2 per 2 cols). A, W fp32 in.
template <int BN>
__global__ void gemm_tf32_kernel(const float* __restrict__ A,
                                 const float* __restrict__ W,
                                 __half* __restrict__ C, int M, int K, int N) {
    constexpr int BM = 128, BK = 16, THREADS = 256;
    constexpr int AS = BK + 4;
    constexpr int WS = BN + 4;
    constexpr int NF = BN / 16;

    __shared__ float As[2][BM * AS];
    __shared__ float Ws[2][BK * WS];

    const int tid = threadIdx.x;
    const int lane = tid & 31;
    const int warp = tid >> 5;
    const int g = lane >> 2;
    const int tg = lane & 3;
    const int wrb = (warp & 3) * 32;
    const int wcb = (warp >> 2) * (BN / 2);
    const int brow = blockIdx.y * BM;
    const int bcol = blockIdx.x * BN;

    float c[2][NF][4];
#pragma unroll
    for (int mi = 0; mi < 2; mi++)
#pragma unroll
        for (int ni = 0; ni < NF; ni++)
#pragma unroll
            for (int j = 0; j < 4; j++) c[mi][ni][j] = 0.0f;

    for (int k0 = 0; k0 < K; k0 += BK) {
#pragma unroll
        for (int p = tid; p < BM * BK / 4; p += THREADS) {
            int r = p / (BK / 4);
            int cc = (p % (BK / 4)) * 4;
            int gr = brow + r;
            float4 v = (gr < M) ? *(const float4*)&A[(size_t)gr * K + k0 + cc]
                                : make_float4(0.f, 0.f, 0.f, 0.f);
            const float vv[4] = {v.x, v.y, v.z, v.w};
#pragma unroll
            for (int j = 0; j < 4; j++) {
                uint32_t big = f2tf32(vv[j]);
                float res = vv[j] - __uint_as_float(big);
                As[0][r * AS + cc + j] = __uint_as_float(big);
                As[1][r * AS + cc + j] = __uint_as_float(f2tf32(res));
            }
        }
#pragma unroll
        for (int p = tid; p < BK * BN / 4; p += THREADS) {
            int r = p / (BN / 4);
            int cc = (p % (BN / 4)) * 4;
            float4 v = *(const float4*)&W[(size_t)(k0 + r) * N + bcol + cc];
            const float vv[4] = {v.x, v.y, v.z, v.w};
#pragma unroll
            for (int j = 0; j < 4; j++) {
                uint32_t big = f2tf32(vv[j]);
                float res = vv[j] - __uint_as_float(big);
                Ws[0][r * WS + cc + j] = __uint_as_float(big);
                Ws[1][r * WS + cc + j] = __uint_as_float(f2tf32(res));
            }
        }
        __syncthreads();

#pragma unroll
        for (int ks = 0; ks < BK / 8; ks++) {
            const int kb = ks * 8;
            uint32_t Ab[2][4], Ar[2][4];
#pragma unroll
            for (int mi = 0; mi < 2; mi++) {
                int r0 = wrb + mi * 16 + g;
                Ab[mi][0] = __float_as_uint(As[0][r0 * AS + kb + tg]);
                Ab[mi][1] = __float_as_uint(As[0][(r0 + 8) * AS + kb + tg]);
                Ab[mi][2] = __float_as_uint(As[0][r0 * AS + kb + tg + 4]);
                Ab[mi][3] = __float_as_uint(As[0][(r0 + 8) * AS + kb + tg + 4]);
                Ar[mi][0] = __float_as_uint(As[1][r0 * AS + kb + tg]);
                Ar[mi][1] = __float_as_uint(As[1][(r0 + 8) * AS + kb + tg]);
                Ar[mi][2] = __float_as_uint(As[1][r0 * AS + kb + tg + 4]);
                Ar[mi][3] = __float_as_uint(As[1][(r0 + 8) * AS + kb + tg + 4]);
            }
#pragma unroll
            for (int ni = 0; ni < NF; ni++) {
                int col = wcb + ni * 8 + g;
                uint32_t Bb0 = __float_as_uint(Ws[0][(kb + tg) * WS + col]);
                uint32_t Bb1 = __float_as_uint(Ws[0][(kb + tg + 4) * WS + col]);
                uint32_t Br0 = __float_as_uint(Ws[1][(kb + tg) * WS + col]);
                uint32_t Br1 = __float_as_uint(Ws[1][(kb + tg + 4) * WS + col]);
#pragma unroll
                for (int mi = 0; mi < 2; mi++) {
                    mma_tf32(c[mi][ni], Ab[mi], Bb0, Bb1);
                    mma_tf32(c[mi][ni], Ar[mi], Bb0, Bb1);
                    mma_tf32(c[mi][ni], Ab[mi], Br0, Br1);
                }
            }
        }
        __syncthreads();
    }

#pragma unroll
    for (int mi = 0; mi < 2; mi++) {
        int gr0 = brow + wrb + mi * 16 + g;
        int gr1 = gr0 + 8;
#pragma unroll
        for (int ni = 0; ni < NF; ni++) {
            int gc = bcol + wcb + ni * 8 + 2 * tg;
            if (gr0 < M)
                *(__half2*)&C[(size_t)gr0 * N + gc] =
                    __floats2half2_rn(c[mi][ni][0], c[mi][ni][1]);
            if (gr1 < M)
                *(__half2*)&C[(size_t)gr1 * N + gc] =
                    __floats2half2_rn(c[mi][ni][2], c[mi][ni][3]);
        }
    }
}

// --------------------------- SIMT GEMM (layer 3, fp32) ---------------------

template <int BM, int BN, int BK, int TM, int TN>
__global__ void gemm_kernel(const float* __restrict__ A,
                            const float* __restrict__ W,
                            float* __restrict__ C, int M, int K, int N) {
    constexpr int THREADS = (BM / TM) * (BN / TN);
    __shared__ float As[BK][BM];
    __shared__ float Ws[BK][BN];

    const int block_row = blockIdx.y * BM;
    const int block_col = blockIdx.x * BN;
    const int tid = threadIdx.x;
    const int tx = tid % (BN / TN);
    const int ty = tid / (BN / TN);

    constexpr int A_F4_PER_ROW = BK / 4;
    const int a_row0 = tid / A_F4_PER_ROW;
    const int a_col = (tid % A_F4_PER_ROW) * 4;
    constexpr int A_ROW_STRIDE = THREADS / A_F4_PER_ROW;

    constexpr int W_F4_PER_ROW = BN / 4;
    const int w_row0 = tid / W_F4_PER_ROW;
    const int w_col = (tid % W_F4_PER_ROW) * 4;
    constexpr int W_ROW_STRIDE = THREADS / W_F4_PER_ROW;

    float acc[TM][TN];
#pragma unroll
    for (int i = 0; i < TM; i++)
#pragma unroll
        for (int j = 0; j < TN; j++) acc[i][j] = 0.0f;

    for (int k0 = 0; k0 < K; k0 += BK) {
#pragma unroll
        for (int r = a_row0; r < BM; r += A_ROW_STRIDE) {
            int gr = block_row + r;
            float4 v = (gr < M)
                ? *(const float4*)&A[(size_t)gr * K + k0 + a_col]
                : make_float4(0.f, 0.f, 0.f, 0.f);
            As[a_col + 0][r] = v.x;
            As[a_col + 1][r] = v.y;
            As[a_col + 2][r] = v.z;
            As[a_col + 3][r] = v.w;
        }
#pragma unroll
        for (int r = w_row0; r < BK; r += W_ROW_STRIDE) {
            *(float4*)&Ws[r][w_col] =
                *(const float4*)&W[(size_t)(k0 + r) * N + block_col + w_col];
        }
        __syncthreads();

#pragma unroll
        for (int k = 0; k < BK; k++) {
            float ra[TM], rb[TN];
#pragma unroll
            for (int i = 0; i < TM; i += 4)
                *(float4*)&ra[i] = *(const float4*)&As[k][ty * TM + i];
#pragma unroll
            for (int j = 0; j < TN; j += 4)
                *(float4*)&rb[j] = *(const float4*)&Ws[k][tx * TN + j];
#pragma unroll
            for (int i = 0; i < TM; i++)
#pragma unroll
                for (int j = 0; j < TN; j++) acc[i][j] += ra[i] * rb[j];
        }
        __syncthreads();
    }

#pragma unroll
    for (int i = 0; i < TM; i++) {
        int gr = block_row + ty * TM + i;
        if (gr < M) {
#pragma unroll
            for (int j = 0; j < TN; j += 4)
                *(float4*)&C[(size_t)gr * N + block_col + tx * TN + j] =
                    *(float4*)&acc[i][j];
        }
    }
}

// ------------------------ gather aggregation (fp16 H) ----------------------
// LPN = D/4 lanes per node; lane owns 4 cols (one half4 = 8B load per edge).
// acc = b + dinv^2*H[i] + sum_e norm_e*H[src_e]; fp32 accumulation.

template <int D, bool RELU>
__global__ void agg_gather_f16_kernel(float* __restrict__ out,
                                      const __half* __restrict__ H,
                                      const float* __restrict__ b, int n) {
    constexpr int LPN = D / 4;
    constexpr int NPW = 32 / LPN;
    int warp = (blockIdx.x * blockDim.x + threadIdx.x) >> 5;
    int lane = threadIdx.x & 31;
    int grp = lane / LPN;
    int f = lane % LPN;
    int i = warp * NPW + grp;
    if (i >= n) return;

    float di = g_dinv[i];
    float s2 = di * di;
    uint2 hp = *(const uint2*)&H[(size_t)i * D + 4 * f];
    float2 h01 = __half22float2(*(__half2*)&hp.x);
    float2 h23 = __half22float2(*(__half2*)&hp.y);
    float4 bb = ((const float4*)b)[f];
    float4 acc;
    acc.x = bb.x + s2 * h01.x;
    acc.y = bb.y + s2 * h01.y;
    acc.z = bb.z + s2 * h23.x;
    acc.w = bb.w + s2 * h23.y;

    int beg = g_offs[i], end = g_offs[i + 1];
#pragma unroll 4
    for (int e = beg; e < end; e++) {
        float2 p = __ldg(&g_csr[e]);
        int s = __float_as_int(p.x);
        float nrm = p.y;
        uint2 vp = *(const uint2*)&H[(size_t)s * D + 4 * f];
        float2 v01 = __half22float2(*(__half2*)&vp.x);
        float2 v23 = __half22float2(*(__half2*)&vp.y);
        acc.x += nrm * v01.x;
        acc.y += nrm * v01.y;
        acc.z += nrm * v23.x;
        acc.w += nrm * v23.y;
    }

    if (RELU) {
        acc.x = fmaxf(acc.x, 0.0f);
        acc.y = fmaxf(acc.y, 0.0f);
        acc.z = fmaxf(acc.z, 0.0f);
        acc.w = fmaxf(acc.w, 0.0f);
    }

    ((float4*)out)[(size_t)i * LPN + f] = acc;
}

// ------------------------ gather aggregation (fp32, layer 3) ---------------

template <int D, bool SOFTMAX>
__global__ void agg_gather_kernel(float* __restrict__ out,
                                  const float* __restrict__ H,
                                  const float* __restrict__ b, int n) {
    constexpr int LPN = D / 4;
    constexpr int NPW = 32 / LPN;
    int warp = (blockIdx.x * blockDim.x + threadIdx.x) >> 5;
    int lane = threadIdx.x & 31;
    int grp = lane / LPN;
    int f = lane % LPN;
    int i = warp * NPW + grp;
    if (i >= n) return;

    float di = g_dinv[i];
    float s2 = di * di;
    float4 h = ((const float4*)H)[(size_t)i * LPN + f];
    float4 bb = ((const float4*)b)[f];
    float4 acc;
    acc.x = bb.x + s2 * h.x;
    acc.y = bb.y + s2 * h.y;
    acc.z = bb.z + s2 * h.z;
    acc.w = bb.w + s2 * h.w;

    int beg = g_offs[i], end = g_offs[i + 1];
#pragma unroll 4
    for (int e = beg; e < end; e++) {
        float2 p = __ldg(&g_csr[e]);
        int s = __float_as_int(p.x);
        float nrm = p.y;
        float4 v = ((const float4*)H)[(size_t)s * LPN + f];
        acc.x += nrm * v.x;
        acc.y += nrm * v.y;
        acc.z += nrm * v.z;
        acc.w += nrm * v.w;
    }

    if (SOFTMAX) {
        float m = fmaxf(fmaxf(acc.x, acc.y), fmaxf(acc.z, acc.w));
#pragma unroll
        for (int o = 1; o < LPN; o <<= 1)
            m = fmaxf(m, __shfl_xor_sync(0xFFFFFFFFu, m, o, LPN));
        acc.x = __expf(acc.x - m);
        acc.y = __expf(acc.y - m);
        acc.z = __expf(acc.z - m);
        acc.w = __expf(acc.w - m);
        float s = acc.x + acc.y + acc.z + acc.w;
#pragma unroll
        for (int o = 1; o < LPN; o <<= 1)
            s += __shfl_xor_sync(0xFFFFFFFFu, s, o, LPN);
        float inv = 1.0f / s;
        acc.x *= inv;
        acc.y *= inv;
        acc.z *= inv;
        acc.w *= inv;
    }

    ((float4*)out)[(size_t)i * LPN + f] = acc;
}

// ------------------------------- launch -----------------------------------

static cudaStream_t s_gemm = nullptr;
static cudaEvent_t  s_evFork = nullptr, s_evJoin = nullptr;

extern "C" void kernel_launch(void* const* d_in, const int* in_sizes, int n_in,
                              void* d_out, int out_size) {
    const float* x  = (const float*)d_in[0];
    const int*   ei = (const int*)d_in[1];   // int32 (JAX x64 disabled)
    const float* W1 = (const float*)d_in[2];
    const float* b1 = (const float*)d_in[3];
    const float* W2 = (const float*)d_in[4];
    const float* b2 = (const float*)d_in[5];
    const float* W3 = (const float*)d_in[6];
    const float* b3 = (const float*)d_in[7];

    const int n = in_sizes[0] / 128;
    const int E = in_sizes[1] / 2;
    const int* src = ei;
    const int* dst = ei + E;

    float *H, *A, *B;
    __half* H16;
    int* degp;
    cudaGetSymbolAddress((void**)&H16, g_H16);
    cudaGetSymbolAddress((void**)&H, g_H);
    cudaGetSymbolAddress((void**)&A, g_A);
    cudaGetSymbolAddress((void**)&B, g_B);
    cudaGetSymbolAddress((void**)&degp, g_deg);

    if (s_gemm == nullptr) {
        cudaStreamCreateWithFlags(&s_gemm, cudaStreamNonBlocking);
        cudaEventCreateWithFlags(&s_evFork, cudaEventDisableTiming);
        cudaEventCreateWithFlags(&s_evJoin, cudaEventDisableTiming);
    }

    const int T = 256;
    auto blocks = [&](long long work) { return (int)((work + T - 1) / T); };
    const int nScanBlocks = (n + SCAN_B - 1) / SCAN_B;
    const int gy = (n + 127) / 128;

    // Fork: layer-1 GEMM (independent of CSR) on side stream.
    cudaEventRecord(s_evFork, 0);
    cudaStreamWaitEvent(s_gemm, s_evFork, 0);
    gemm_tf32_kernel<128><<<dim3(1, gy), 256, 0, s_gemm>>>(x, W1, H16, n, 128, 128);
    cudaEventRecord(s_evJoin, s_gemm);

    // CSR build on main stream (concurrent with GEMM1).
    cudaMemsetAsync(degp, 0, (size_t)n * sizeof(int), 0);
    deg_kernel<<<blocks(E), T>>>(dst, E);
    scan1_kernel<<<nScanBlocks, SCAN_B>>>(n);
    scan3_kernel<<<blocks(n + 1), T>>>(n, E, nScanBlocks);
    scatter_kernel<<<blocks(E), T>>>(src, dst, E);

    // Join: gather1 needs both CSR and H.
    cudaStreamWaitEvent(0, s_evJoin, 0);

    // ----- layer 1 aggregation (fp16 gather, relu fused) -----
    agg_gather_f16_kernel<128, true>
        <<<blocks((long long)n * 32), T>>>(A, H16, b1, n);

    // ----- layer 2: 128 -> 64 (tf32 TC -> fp16 H) -----
    gemm_tf32_kernel<64><<<dim3(1, gy), 256>>>(A, W2, H16, n, 128, 64);
    agg_gather_f16_kernel<64, false>
        <<<blocks((long long)n * 16), T>>>(B, H16, b2, n);

    // ----- layer 3: 64 -> 16 (SIMT fp32) + softmax -> d_out -----
    gemm_kernel<128, 16, 16, 4, 4><<<dim3(1, gy), 128>>>(B, W3, H, n, 64, 16);
    agg_gather_kernel<16, true>
        <<<blocks((long long)n * 4), T>>>((float*)d_out, H, b3, n);
}

// round 8
// speedup vs baseline: 3.3737x; 1.0393x over previous
#include <cuda_runtime.h>
#include <cuda_fp16.h>
#include <cstdint>

// ---------------------------------------------------------------------------
// ExtendedGCN: 3-layer GCN (PyG GCNConv) + softmax.
//   Pull-based (atomic-free) aggregation over per-call CSR-by-dst with packed
//   (src, norm) payload.  Layers 1/2 GEMM on tensor cores (split-tf32, fp32
//   accuracy); fp16 intermediates (H1, A1, H2) halve gather/GEMM traffic,
//   fp32 accumulation everywhere.  Layer 3 fully fp32.  relu fused into agg1;
//   softmax into agg3.  CSR build overlapped with layer-1 GEMM (2nd stream).
// edge_index is int32 on device (JAX x64 disabled).
// ---------------------------------------------------------------------------

#define NMAX 50000
#define EMAX 800000
#define SCAN_B 1024
#define NSCANB ((NMAX + SCAN_B - 1) / SCAN_B)

__device__ __half g_H16[(size_t)NMAX * 128];  // fp16 GEMM outputs (layers 1/2)
__device__ __half g_A16[(size_t)NMAX * 128];  // fp16 agg1 output (GEMM2 input)
__device__ float  g_H[(size_t)NMAX * 64];     // fp32 layer-3 GEMM output
__device__ float  g_B[(size_t)NMAX * 64];     // fp32 agg2 output
__device__ float  g_dinv[NMAX];
__device__ int    g_deg[NMAX];
__device__ int    g_offs[NMAX + 1];
__device__ int    g_cursor[NMAX];
__device__ float2 g_csr[EMAX];                // (src as int bits, norm)
__device__ int    g_bsum[NSCANB];

// ----------------------------- CSR build ----------------------------------

__global__ void deg_kernel(const int* __restrict__ dst, int E) {
    int e = blockIdx.x * blockDim.x + threadIdx.x;
    if (e < E) atomicAdd(&g_deg[dst[e]], 1);
}

__global__ void scan1_kernel(int n) {
    __shared__ int warp_tot[32];
    int tid = threadIdx.x;
    int lane = tid & 31;
    int warp = tid >> 5;
    int gid = blockIdx.x * SCAN_B + tid;
    int v = (gid < n) ? g_deg[gid] : 0;
    if (gid < n) g_dinv[gid] = rsqrtf((float)(v + 1));

    int inc = v;
#pragma unroll
    for (int o = 1; o < 32; o <<= 1) {
        int t = __shfl_up_sync(0xFFFFFFFFu, inc, o);
        if (lane >= o) inc += t;
    }
    if (lane == 31) warp_tot[warp] = inc;
    __syncthreads();
    if (warp == 0) {
        int w = warp_tot[lane];
        int wi = w;
#pragma unroll
        for (int o = 1; o < 32; o <<= 1) {
            int t = __shfl_up_sync(0xFFFFFFFFu, wi, o);
            if (lane >= o) wi += t;
        }
        warp_tot[lane] = wi - w;
        if (lane == 31) g_bsum[blockIdx.x] = wi;
    }
    __syncthreads();
    if (gid < n) g_offs[gid] = inc - v + warp_tot[warp];
}

// blocks aligned with scan1 blocks; warp 0 shfl-reduces the <=NSCANB block
// totals before this block, broadcasts via smem. O(NSCANB/32) per warp.
__global__ void scan3_kernel(int n, int E) {
    __shared__ int pre;
    int tid = threadIdx.x;
    if (tid < 32) {
        int acc = 0;
        for (int j = tid; j < (int)blockIdx.x; j += 32) acc += g_bsum[j];
#pragma unroll
        for (int o = 16; o > 0; o >>= 1)
            acc += __shfl_xor_sync(0xFFFFFFFFu, acc, o);
        if (tid == 0) pre = acc;
    }
    __syncthreads();
    int gid = blockIdx.x * SCAN_B + tid;
    if (gid < n) {
        int o = g_offs[gid] + pre;
        g_offs[gid] = o;
        g_cursor[gid] = o;
    }
    if (gid == n) g_offs[n] = E;
}

__global__ void scatter_kernel(const int* __restrict__ src,
                               const int* __restrict__ dst, int E) {
    int e = blockIdx.x * blockDim.x + threadIdx.x;
    if (e < E) {
        int s = src[e], d = dst[e];
        int pos = atomicAdd(&g_cursor[d], 1);
        float nrm = g_dinv[s] * g_dinv[d];
        g_csr[pos] = make_float2(__int_as_float(s), nrm);
    }
}

// ------------------------- tf32 tensor GEMM --------------------------------

__device__ __forceinline__ uint32_t f2tf32(float x) {
    uint32_t r;
    asm("cvt.rna.tf32.f32 %0, %1;" : "=r"(r) : "f"(x));
    return r;
}

__device__ __forceinline__ void mma_tf32(float* c, const uint32_t* a,
                                         uint32_t b0, uint32_t b1) {
    asm volatile(
        "mma.sync.aligned.m16n8k8.row.col.f32.tf32.tf32.f32 "
        "{%0,%1,%2,%3}, {%4,%5,%6,%7}, {%8,%9}, {%0,%1,%2,%3};\n"
        : "+f"(c[0]), "+f"(c[1]), "+f"(c[2]), "+f"(c[3])
        : "r"(a[0]), "r"(a[1]), "r"(a[2]), "r"(a[3]), "r"(b0), "r"(b1));
}

// A: fp32 or fp16 in, W fp32 in, C fp16 out.
template <int BN, typename AT>
__global__ void gemm_tf32_kernel(const AT* __restrict__ A,
                                 const float* __restrict__ W,
                                 __half* __restrict__ C, int M, int K, int N) {
    constexpr int BM = 128, BK = 16, THREADS = 256;
    constexpr int AS = BK + 4;
    constexpr int WS = BN + 4;
    constexpr int NF = BN / 16;
    constexpr bool A_HALF = (sizeof(AT) == 2);

    __shared__ float As[2][BM * AS];
    __shared__ float Ws[2][BK * WS];

    const int tid = threadIdx.x;
    const int lane = tid & 31;
    const int warp = tid >> 5;
    const int g = lane >> 2;
    const int tg = lane & 3;
    const int wrb = (warp & 3) * 32;
    const int wcb = (warp >> 2) * (BN / 2);
    const int brow = blockIdx.y * BM;
    const int bcol = blockIdx.x * BN;

    float c[2][NF][4];
#pragma unroll
    for (int mi = 0; mi < 2; mi++)
#pragma unroll
        for (int ni = 0; ni < NF; ni++)
#pragma unroll
            for (int j = 0; j < 4; j++) c[mi][ni][j] = 0.0f;

    for (int k0 = 0; k0 < K; k0 += BK) {
#pragma unroll
        for (int p = tid; p < BM * BK / 4; p += THREADS) {
            int r = p / (BK / 4);
            int cc = (p % (BK / 4)) * 4;
            int gr = brow + r;
            float vv[4] = {0.f, 0.f, 0.f, 0.f};
            if (gr < M) {
                if (A_HALF) {
                    uint2 hv = *(const uint2*)&A[(size_t)gr * K + k0 + cc];
                    float2 f01 = __half22float2(*(__half2*)&hv.x);
                    float2 f23 = __half22float2(*(__half2*)&hv.y);
                    vv[0] = f01.x; vv[1] = f01.y; vv[2] = f23.x; vv[3] = f23.y;
                } else {
                    float4 v = *(const float4*)&A[(size_t)gr * K + k0 + cc];
                    vv[0] = v.x; vv[1] = v.y; vv[2] = v.z; vv[3] = v.w;
                }
            }
#pragma unroll
            for (int j = 0; j < 4; j++) {
                uint32_t big = f2tf32(vv[j]);
                float res = vv[j] - __uint_as_float(big);
                As[0][r * AS + cc + j] = __uint_as_float(big);
                As[1][r * AS + cc + j] = __uint_as_float(f2tf32(res));
            }
        }
#pragma unroll
        for (int p = tid; p < BK * BN / 4; p += THREADS) {
            int r = p / (BN / 4);
            int cc = (p % (BN / 4)) * 4;
            float4 v = *(const float4*)&W[(size_t)(k0 + r) * N + bcol + cc];
            const float vv[4] = {v.x, v.y, v.z, v.w};
#pragma unroll
            for (int j = 0; j < 4; j++) {
                uint32_t big = f2tf32(vv[j]);
                float res = vv[j] - __uint_as_float(big);
                Ws[0][r * WS + cc + j] = __uint_as_float(big);
                Ws[1][r * WS + cc + j] = __uint_as_float(f2tf32(res));
            }
        }
        __syncthreads();

#pragma unroll
        for (int ks = 0; ks < BK / 8; ks++) {
            const int kb = ks * 8;
            uint32_t Ab[2][4], Ar[2][4];
#pragma unroll
            for (int mi = 0; mi < 2; mi++) {
                int r0 = wrb + mi * 16 + g;
                Ab[mi][0] = __float_as_uint(As[0][r0 * AS + kb + tg]);
                Ab[mi][1] = __float_as_uint(As[0][(r0 + 8) * AS + kb + tg]);
                Ab[mi][2] = __float_as_uint(As[0][r0 * AS + kb + tg + 4]);
                Ab[mi][3] = __float_as_uint(As[0][(r0 + 8) * AS + kb + tg + 4]);
                Ar[mi][0] = __float_as_uint(As[1][r0 * AS + kb + tg]);
                Ar[mi][1] = __float_as_uint(As[1][(r0 + 8) * AS + kb + tg]);
                Ar[mi][2] = __float_as_uint(As[1][r0 * AS + kb + tg + 4]);
                Ar[mi][3] = __float_as_uint(As[1][(r0 + 8) * AS + kb + tg + 4]);
            }
#pragma unroll
            for (int ni = 0; ni < NF; ni++) {
                int col = wcb + ni * 8 + g;
                uint32_t Bb0 = __float_as_uint(Ws[0][(kb + tg) * WS + col]);
                uint32_t Bb1 = __float_as_uint(Ws[0][(kb + tg + 4) * WS + col]);
                uint32_t Br0 = __float_as_uint(Ws[1][(kb + tg) * WS + col]);
                uint32_t Br1 = __float_as_uint(Ws[1][(kb + tg + 4) * WS + col]);
#pragma unroll
                for (int mi = 0; mi < 2; mi++) {
                    mma_tf32(c[mi][ni], Ab[mi], Bb0, Bb1);
                    mma_tf32(c[mi][ni], Ar[mi], Bb0, Bb1);
                    mma_tf32(c[mi][ni], Ab[mi], Br0, Br1);
                }
            }
        }
        __syncthreads();
    }

#pragma unroll
    for (int mi = 0; mi < 2; mi++) {
        int gr0 = brow + wrb + mi * 16 + g;
        int gr1 = gr0 + 8;
#pragma unroll
        for (int ni = 0; ni < NF; ni++) {
            int gc = bcol + wcb + ni * 8 + 2 * tg;
            if (gr0 < M)
                *(__half2*)&C[(size_t)gr0 * N + gc] =
                    __floats2half2_rn(c[mi][ni][0], c[mi][ni][1]);
            if (gr1 < M)
                *(__half2*)&C[(size_t)gr1 * N + gc] =
                    __floats2half2_rn(c[mi][ni][2], c[mi][ni][3]);
        }
    }
}

// --------------------------- SIMT GEMM (layer 3, fp32) ---------------------

template <int BM, int BN, int BK, int TM, int TN>
__global__ void gemm_kernel(const float* __restrict__ A,
                            const float* __restrict__ W,
                            float* __restrict__ C, int M, int K, int N) {
    constexpr int THREADS = (BM / TM) * (BN / TN);
    __shared__ float As[BK][BM];
    __shared__ float Ws[BK][BN];

    const int block_row = blockIdx.y * BM;
    const int block_col = blockIdx.x * BN;
    const int tid = threadIdx.x;
    const int tx = tid % (BN / TN);
    const int ty = tid / (BN / TN);

    constexpr int A_F4_PER_ROW = BK / 4;
    const int a_row0 = tid / A_F4_PER_ROW;
    const int a_col = (tid % A_F4_PER_ROW) * 4;
    constexpr int A_ROW_STRIDE = THREADS / A_F4_PER_ROW;

    constexpr int W_F4_PER_ROW = BN / 4;
    const int w_row0 = tid / W_F4_PER_ROW;
    const int w_col = (tid % W_F4_PER_ROW) * 4;
    constexpr int W_ROW_STRIDE = THREADS / W_F4_PER_ROW;

    float acc[TM][TN];
#pragma unroll
    for (int i = 0; i < TM; i++)
#pragma unroll
        for (int j = 0; j < TN; j++) acc[i][j] = 0.0f;

    for (int k0 = 0; k0 < K; k0 += BK) {
#pragma unroll
        for (int r = a_row0; r < BM; r += A_ROW_STRIDE) {
            int gr = block_row + r;
            float4 v = (gr < M)
                ? *(const float4*)&A[(size_t)gr * K + k0 + a_col]
                : make_float4(0.f, 0.f, 0.f, 0.f);
            As[a_col + 0][r] = v.x;
            As[a_col + 1][r] = v.y;
            As[a_col + 2][r] = v.z;
            As[a_col + 3][r] = v.w;
        }
#pragma unroll
        for (int r = w_row0; r < BK; r += W_ROW_STRIDE) {
            *(float4*)&Ws[r][w_col] =
                *(const float4*)&W[(size_t)(k0 + r) * N + block_col + w_col];
        }
        __syncthreads();

#pragma unroll
        for (int k = 0; k < BK; k++) {
            float ra[TM], rb[TN];
#pragma unroll
            for (int i = 0; i < TM; i += 4)
                *(float4*)&ra[i] = *(const float4*)&As[k][ty * TM + i];
#pragma unroll
            for (int j = 0; j < TN; j += 4)
                *(float4*)&rb[j] = *(const float4*)&Ws[k][tx * TN + j];
#pragma unroll
            for (int i = 0; i < TM; i++)
#pragma unroll
                for (int j = 0; j < TN; j++) acc[i][j] += ra[i] * rb[j];
        }
        __syncthreads();
    }

#pragma unroll
    for (int i = 0; i < TM; i++) {
        int gr = block_row + ty * TM + i;
        if (gr < M) {
#pragma unroll
            for (int j = 0; j < TN; j += 4)
                *(float4*)&C[(size_t)gr * N + block_col + tx * TN + j] =
                    *(float4*)&acc[i][j];
        }
    }
}

// ------------------------ gather aggregation (fp16 H) ----------------------
// LPN = D/4 lanes per node; lane owns 4 cols (8B load per edge).
// fp32 accumulation; output fp32 or fp16 (templated).

template <int D, bool RELU, typename OUT, int UNR>
__global__ void agg_gather_f16_kernel(OUT* __restrict__ out,
                                      const __half* __restrict__ H,
                                      const float* __restrict__ b, int n) {
    constexpr int LPN = D / 4;
    constexpr int NPW = 32 / LPN;
    int warp = (blockIdx.x * blockDim.x + threadIdx.x) >> 5;
    int lane = threadIdx.x & 31;
    int grp = lane / LPN;
    int f = lane % LPN;
    int i = warp * NPW + grp;
    if (i >= n) return;

    float di = g_dinv[i];
    float s2 = di * di;
    uint2 hp = *(const uint2*)&H[(size_t)i * D + 4 * f];
    float2 h01 = __half22float2(*(__half2*)&hp.x);
    float2 h23 = __half22float2(*(__half2*)&hp.y);
    float4 bb = ((const float4*)b)[f];
    float4 acc;
    acc.x = bb.x + s2 * h01.x;
    acc.y = bb.y + s2 * h01.y;
    acc.z = bb.z + s2 * h23.x;
    acc.w = bb.w + s2 * h23.y;

    int beg = g_offs[i], end = g_offs[i + 1];
#pragma unroll UNR
    for (int e = beg; e < end; e++) {
        float2 p = __ldg(&g_csr[e]);
        int s = __float_as_int(p.x);
        float nrm = p.y;
        uint2 vp = *(const uint2*)&H[(size_t)s * D + 4 * f];
        float2 v01 = __half22float2(*(__half2*)&vp.x);
        float2 v23 = __half22float2(*(__half2*)&vp.y);
        acc.x += nrm * v01.x;
        acc.y += nrm * v01.y;
        acc.z += nrm * v23.x;
        acc.w += nrm * v23.y;
    }

    if (RELU) {
        acc.x = fmaxf(acc.x, 0.0f);
        acc.y = fmaxf(acc.y, 0.0f);
        acc.z = fmaxf(acc.z, 0.0f);
        acc.w = fmaxf(acc.w, 0.0f);
    }

    if (sizeof(OUT) == 2) {
        uint2 o;
        *(__half2*)&o.x = __floats2half2_rn(acc.x, acc.y);
        *(__half2*)&o.y = __floats2half2_rn(acc.z, acc.w);
        *(uint2*)&out[(size_t)i * D + 4 * f] = o;
    } else {
        ((float4*)out)[(size_t)i * LPN + f] = acc;
    }
}

// ------------------------ gather aggregation (fp32, layer 3) ---------------

template <int D, bool SOFTMAX>
__global__ void agg_gather_kernel(float* __restrict__ out,
                                  const float* __restrict__ H,
                                  const float* __restrict__ b, int n) {
    constexpr int LPN = D / 4;
    constexpr int NPW = 32 / LPN;
    int warp = (blockIdx.x * blockDim.x + threadIdx.x) >> 5;
    int lane = threadIdx.x & 31;
    int grp = lane / LPN;
    int f = lane % LPN;
    int i = warp * NPW + grp;
    if (i >= n) return;

    float di = g_dinv[i];
    float s2 = di * di;
    float4 h = ((const float4*)H)[(size_t)i * LPN + f];
    float4 bb = ((const float4*)b)[f];
    float4 acc;
    acc.x = bb.x + s2 * h.x;
    acc.y = bb.y + s2 * h.y;
    acc.z = bb.z + s2 * h.z;
    acc.w = bb.w + s2 * h.w;

    int beg = g_offs[i], end = g_offs[i + 1];
#pragma unroll 4
    for (int e = beg; e < end; e++) {
        float2 p = __ldg(&g_csr[e]);
        int s = __float_as_int(p.x);
        float nrm = p.y;
        float4 v = ((const float4*)H)[(size_t)s * LPN + f];
        acc.x += nrm * v.x;
        acc.y += nrm * v.y;
        acc.z += nrm * v.z;
        acc.w += nrm * v.w;
    }

    if (SOFTMAX) {
        float m = fmaxf(fmaxf(acc.x, acc.y), fmaxf(acc.z, acc.w));
#pragma unroll
        for (int o = 1; o < LPN; o <<= 1)
            m = fmaxf(m, __shfl_xor_sync(0xFFFFFFFFu, m, o, LPN));
        acc.x = __expf(acc.x - m);
        acc.y = __expf(acc.y - m);
        acc.z = __expf(acc.z - m);
        acc.w = __expf(acc.w - m);
        float s = acc.x + acc.y + acc.z + acc.w;
#pragma unroll
        for (int o = 1; o < LPN; o <<= 1)
            s += __shfl_xor_sync(0xFFFFFFFFu, s, o, LPN);
        float inv = 1.0f / s;
        acc.x *= inv;
        acc.y *= inv;
        acc.z *= inv;
        acc.w *= inv;
    }

    ((float4*)out)[(size_t)i * LPN + f] = acc;
}

// ------------------------------- launch -----------------------------------

static cudaStream_t s_gemm = nullptr;
static cudaEvent_t  s_evFork = nullptr, s_evJoin = nullptr;

extern "C" void kernel_launch(void* const* d_in, const int* in_sizes, int n_in,
                              void* d_out, int out_size) {
    const float* x  = (const float*)d_in[0];
    const int*   ei = (const int*)d_in[1];   // int32 (JAX x64 disabled)
    const float* W1 = (const float*)d_in[2];
    const float* b1 = (const float*)d_in[3];
    const float* W2 = (const float*)d_in[4];
    const float* b2 = (const float*)d_in[5];
    const float* W3 = (const float*)d_in[6];
    const float* b3 = (const float*)d_in[7];

    const int n = in_sizes[0] / 128;
    const int E = in_sizes[1] / 2;
    const int* src = ei;
    const int* dst = ei + E;

    float *H, *B;
    __half *H16, *A16;
    int* degp;
    cudaGetSymbolAddress((void**)&H16, g_H16);
    cudaGetSymbolAddress((void**)&A16, g_A16);
    cudaGetSymbolAddress((void**)&H, g_H);
    cudaGetSymbolAddress((void**)&B, g_B);
    cudaGetSymbolAddress((void**)&degp, g_deg);

    if (s_gemm == nullptr) {
        cudaStreamCreateWithFlags(&s_gemm, cudaStreamNonBlocking);
        cudaEventCreateWithFlags(&s_evFork, cudaEventDisableTiming);
        cudaEventCreateWithFlags(&s_evJoin, cudaEventDisableTiming);
    }

    const int T = 256;
    auto blocks = [&](long long work) { return (int)((work + T - 1) / T); };
    const int nScanBlocks = (n + SCAN_B - 1) / SCAN_B;
    const int gy = (n + 127) / 128;

    // Fork: layer-1 GEMM (independent of CSR) on side stream.
    cudaEventRecord(s_evFork, 0);
    cudaStreamWaitEvent(s_gemm, s_evFork, 0);
    gemm_tf32_kernel<128, float>
        <<<dim3(1, gy), 256, 0, s_gemm>>>(x, W1, H16, n, 128, 128);
    cudaEventRecord(s_evJoin, s_gemm);

    // CSR build on main stream (concurrent with GEMM1).
    cudaMemsetAsync(degp, 0, (size_t)n * sizeof(int), 0);
    deg_kernel<<<blocks(E), T>>>(dst, E);
    scan1_kernel<<<nScanBlocks, SCAN_B>>>(n);
    scan3_kernel<<<nScanBlocks, SCAN_B>>>(n, E);
    scatter_kernel<<<blocks(E), T>>>(src, dst, E);

    // Join: gather1 needs both CSR and H.
    cudaStreamWaitEvent(0, s_evJoin, 0);

    // ----- layer 1 aggregation (fp16 in/out, relu fused) -----
    agg_gather_f16_kernel<128, true, __half, 8>
        <<<blocks((long long)n * 32), T>>>(A16, H16, b1, n);

    // ----- layer 2: 128 -> 64 (tf32 TC, fp16 in -> fp16 H) -----
    gemm_tf32_kernel<64, __half>
        <<<dim3(1, gy), 256>>>(A16, W2, H16, n, 128, 64);
    agg_gather_f16_kernel<64, false, float, 4>
        <<<blocks((long long)n * 16), T>>>(B, H16, b2, n);

    // ----- layer 3: 64 -> 16 (SIMT fp32) + softmax -> d_out -----
    gemm_kernel<128, 16, 16, 4, 4><<<dim3(1, gy), 128>>>(B, W3, H, n, 64, 16);
    agg_gather_kernel<16, true>
        <<<blocks((long long)n * 4), T>>>((float*)d_out, H, b3, n);
}